// round 11
// baseline (speedup 1.0000x reference)
#include <cuda_runtime.h>
#include <cuda_bf16.h>
#include <math.h>
#include <stdint.h>

// ---------------- problem constants ----------------
#define HID 4096
#define NH  32
#define NKV 8
#define HD  128
#define MAX_NNZ 4096
#define MAX_S   1024

// ---------------- device scratch (no allocs allowed) ----------------
__device__ float g_q   [(size_t)MAX_NNZ * NH  * HD];
__device__ float g_kt  [(size_t)MAX_NNZ * NKV * HD];
__device__ float g_vt  [(size_t)MAX_NNZ * NKV * HD];
__device__ float g_kg  [(size_t)MAX_NNZ * NKV * HD];
__device__ float g_vg  [(size_t)MAX_NNZ * NKV * HD];
__device__ float g_attn[(size_t)MAX_NNZ * NH  * HD];
__device__ float g_cos [MAX_S * 64];
__device__ float g_sin [MAX_S * 64];

__device__ __nv_bfloat16 g_hs_hi[(size_t)MAX_NNZ * HID];
__device__ __nv_bfloat16 g_hs_lo[(size_t)MAX_NNZ * HID];
__device__ __nv_bfloat16 g_wq_hi[(size_t)NH  * HD * HID];
__device__ __nv_bfloat16 g_wq_lo[(size_t)NH  * HD * HID];
__device__ __nv_bfloat16 g_wk_hi[(size_t)NKV * HD * HID];
__device__ __nv_bfloat16 g_wk_lo[(size_t)NKV * HD * HID];
__device__ __nv_bfloat16 g_wv_hi[(size_t)NKV * HD * HID];
__device__ __nv_bfloat16 g_wv_lo[(size_t)NKV * HD * HID];
__device__ __nv_bfloat16 g_wo_hi[(size_t)HID * NH * HD];
__device__ __nv_bfloat16 g_wo_lo[(size_t)HID * NH * HD];
__device__ __nv_bfloat16 g_at_hi[(size_t)MAX_NNZ * NH * HD];
__device__ __nv_bfloat16 g_at_lo[(size_t)MAX_NNZ * NH * HD];

// ---------------- helpers ----------------
__device__ __forceinline__ uint32_t smem_u32(const void* p) {
    uint32_t a;
    asm("{ .reg .u64 t; cvta.to.shared.u64 t, %1; cvt.u32.u64 %0, t; }" : "=r"(a) : "l"(p));
    return a;
}
// SW64 swizzle for 64-byte rows (BK=32 bf16): conflict-free ldmatrix
#define SWZ64(o) ((o) ^ (((o) >> 3) & 0x30))

__device__ __forceinline__ void mma16816(float* c, const uint32_t* a, const uint32_t* b) {
    asm volatile(
        "mma.sync.aligned.m16n8k16.row.col.f32.bf16.bf16.f32 "
        "{%0,%1,%2,%3}, {%4,%5,%6,%7}, {%8,%9}, {%0,%1,%2,%3};\n"
        : "+f"(c[0]), "+f"(c[1]), "+f"(c[2]), "+f"(c[3])
        : "r"(a[0]), "r"(a[1]), "r"(a[2]), "r"(a[3]), "r"(b[0]), "r"(b[1]));
}
__device__ __forceinline__ void ldsm4(uint32_t* r, uint32_t addr) {
    asm volatile("ldmatrix.sync.aligned.m8n8.x4.shared.b16 {%0,%1,%2,%3}, [%4];"
        : "=r"(r[0]), "=r"(r[1]), "=r"(r[2]), "=r"(r[3]) : "r"(addr));
}
__device__ __forceinline__ void cp16(uint32_t dst, const void* src) {
    asm volatile("cp.async.cg.shared.global [%0], [%1], 16;" :: "r"(dst), "l"(src));
}

// ---------------- fp32 -> (bf16 hi, bf16 lo) split ----------------
__global__ void cvt_split_kernel(const float* __restrict__ x,
                                 __nv_bfloat16* __restrict__ hi,
                                 __nv_bfloat16* __restrict__ lo, int n4) {
    int i = blockIdx.x * blockDim.x + threadIdx.x;
    if (i >= n4) return;
    float4 v = ((const float4*)x)[i];
    union { __nv_bfloat16 b[4]; uint2 u; } H, L;
    H.b[0] = __float2bfloat16_rn(v.x);
    H.b[1] = __float2bfloat16_rn(v.y);
    H.b[2] = __float2bfloat16_rn(v.z);
    H.b[3] = __float2bfloat16_rn(v.w);
    L.b[0] = __float2bfloat16_rn(v.x - __bfloat162float(H.b[0]));
    L.b[1] = __float2bfloat16_rn(v.y - __bfloat162float(H.b[1]));
    L.b[2] = __float2bfloat16_rn(v.z - __bfloat162float(H.b[2]));
    L.b[3] = __float2bfloat16_rn(v.w - __bfloat162float(H.b[3]));
    ((uint2*)hi)[i] = H.u;
    ((uint2*)lo)[i] = L.u;
}

// ---------------- RoPE table ----------------
__global__ void rope_table_kernel() {
    int p = blockIdx.x;
    int j = threadIdx.x;
    double e    = (double)j / 64.0;
    double freq = exp(-e * log(500000.0));
    const double PI = 3.14159265358979323846;
    double wavelen = 2.0 * PI / freq;
    double f;
    if (wavelen < 2048.0)       f = freq;
    else if (wavelen > 8192.0)  f = freq / 8.0;
    else {
        double smooth = (8192.0 / wavelen - 1.0) / 3.0;
        f = (1.0 - smooth) * freq / 8.0 + smooth * freq;
    }
    double ang = (double)p * f;
    g_cos[p * 64 + j] = (float)cos(ang);
    g_sin[p * 64 + j] = (float)sin(ang);
}

__global__ void rope_q_kernel(float* __restrict__ q, const int* __restrict__ pos) {
    int i = blockIdx.x;
    int p = pos[i];
    const float* cr = g_cos + (size_t)p * 64;
    const float* sr = g_sin + (size_t)p * 64;
    float* base = q + (size_t)i * (NH * HD);
    for (int idx = threadIdx.x; idx < NH * 64; idx += blockDim.x) {
        int h = idx >> 6, j = idx & 63;
        float c = cr[j], s = sr[j];
        float* hb = base + h * HD;
        float x1 = hb[j], x2 = hb[j + 64];
        hb[j]      = x1 * c - x2 * s;
        hb[j + 64] = x2 * c + x1 * s;
    }
}

__global__ void ropekv_scatter_kernel(const int* __restrict__ pos, int s_per_b) {
    int i = blockIdx.x;
    int b = i / s_per_b;
    int p = pos[i];
    int dst = b * s_per_b + p;
    const float* cr = g_cos + (size_t)p * 64;
    const float* sr = g_sin + (size_t)p * 64;
    const float* kin  = g_kt + (size_t)i   * (NKV * HD);
    float*       kout = g_kg + (size_t)dst * (NKV * HD);
    for (int idx = threadIdx.x; idx < NKV * 64; idx += blockDim.x) {
        int h = idx >> 6, j = idx & 63;
        float c = cr[j], s = sr[j];
        float x1 = kin[h * HD + j], x2 = kin[h * HD + j + 64];
        kout[h * HD + j]      = x1 * c - x2 * s;
        kout[h * HD + j + 64] = x2 * c + x1 * s;
    }
    const float* vin  = g_vt + (size_t)i   * (NKV * HD);
    float*       vout = g_vg + (size_t)dst * (NKV * HD);
    for (int idx = threadIdx.x; idx < NKV * HD; idx += blockDim.x)
        vout[idx] = vin[idx];
}

// ================= HMMA split-bf16 GEMM core =================
// C[.,N] tile at (m0,n0) = A[M,K] * B[N,K]^T via 3xBF16 (hh + hl + lh).
// BM=BN=128, BK=32. 256 threads = 8 warps (4m x 2n), warp tile 32x64.
// 4-stage cp.async pipeline (3 in flight), SW64 smem, ldmatrix loads.
#define BM 128
#define BN 128
#define BK 32
#define NSTAGE   4
#define ST_BYTES (32 * 1024)
#define OFF_AH   0
#define OFF_AL   (8 * 1024)
#define OFF_BH   (16 * 1024)
#define OFF_BL   (24 * 1024)
#define GEMM_SMEM (NSTAGE * ST_BYTES)

__device__ __forceinline__ void load_stage(
    uint32_t sb, int tid,
    const __nv_bfloat16* __restrict__ Ahi, const __nv_bfloat16* __restrict__ Alo,
    const __nv_bfloat16* __restrict__ Bhi, const __nv_bfloat16* __restrict__ Blo,
    int m0, int n0, int K, int k0) {
#pragma unroll
    for (int j = 0; j < 2; ++j) {
        int idx = tid + j * 256;              // 0..511: 128 rows x 4 chunks
        int r = idx >> 2, c = idx & 3;
        uint32_t off = SWZ64((uint32_t)(r * 64 + c * 16));
        const size_t ga = (size_t)(m0 + r) * K + k0 + c * 8;
        cp16(sb + OFF_AH + off, Ahi + ga);
        cp16(sb + OFF_AL + off, Alo + ga);
        const size_t gb = (size_t)(n0 + r) * K + k0 + c * 8;
        cp16(sb + OFF_BH + off, Bhi + gb);
        cp16(sb + OFF_BL + off, Blo + gb);
    }
    asm volatile("cp.async.commit_group;" ::: "memory");
}

__device__ __forceinline__ void gemm_core(
    uint32_t smb,
    const __nv_bfloat16* __restrict__ Ahi, const __nv_bfloat16* __restrict__ Alo,
    const __nv_bfloat16* __restrict__ Bhi, const __nv_bfloat16* __restrict__ Blo,
    float* __restrict__ C, int m0, int n0, int N, int K) {
    const int tid  = threadIdx.x;
    const int wid  = tid >> 5;
    const int lane = tid & 31;
    const int wm = (wid & 3) << 5;    // 0,32,64,96
    const int wn = (wid >> 2) << 6;   // 0,64

    const int a_row0 = wm + (lane & 15);
    const int a_csel = lane >> 4;
    const int b_row0 = wn + (lane & 7) + ((lane >> 4) << 3);
    const int b_csel = (lane >> 3) & 1;

    float acc[2][8][4];
#pragma unroll
    for (int mi = 0; mi < 2; ++mi)
#pragma unroll
        for (int ni = 0; ni < 8; ++ni)
#pragma unroll
            for (int r = 0; r < 4; ++r) acc[mi][ni][r] = 0.f;

    const int NIT = K / BK;
#pragma unroll
    for (int st = 0; st < NSTAGE - 1; ++st)
        load_stage(smb + st * ST_BYTES, tid, Ahi, Alo, Bhi, Blo, m0, n0, K, st * BK);

    for (int it = 0; it < NIT; ++it) {
        if (it + 2 < NIT)       asm volatile("cp.async.wait_group 2;" ::: "memory");
        else if (it + 1 < NIT)  asm volatile("cp.async.wait_group 1;" ::: "memory");
        else                    asm volatile("cp.async.wait_group 0;" ::: "memory");
        __syncthreads();        // stage `it` visible; compute of it-1 done by all

        if (it + NSTAGE - 1 < NIT)
            load_stage(smb + ((it + NSTAGE - 1) & (NSTAGE - 1)) * ST_BYTES, tid,
                       Ahi, Alo, Bhi, Blo, m0, n0, K, (it + NSTAGE - 1) * BK);

        const uint32_t sb = smb + (it & (NSTAGE - 1)) * ST_BYTES;
#pragma unroll
        for (int ks = 0; ks < 2; ++ks) {      // two k16 steps per BK=32
            uint32_t ah[2][4], al[2][4], bh[4][4], bl[4][4];
#pragma unroll
            for (int mi = 0; mi < 2; ++mi) {
                uint32_t off = SWZ64((uint32_t)((a_row0 + mi * 16) * 64 + (ks * 2 + a_csel) * 16));
                ldsm4(ah[mi], sb + OFF_AH + off);
                ldsm4(al[mi], sb + OFF_AL + off);
            }
#pragma unroll
            for (int ni2 = 0; ni2 < 4; ++ni2) {
                uint32_t off = SWZ64((uint32_t)((b_row0 + ni2 * 16) * 64 + (ks * 2 + b_csel) * 16));
                ldsm4(bh[ni2], sb + OFF_BH + off);
                ldsm4(bl[ni2], sb + OFF_BL + off);
            }
#pragma unroll
            for (int ni = 0; ni < 8; ++ni)
#pragma unroll
                for (int mi = 0; mi < 2; ++mi)
                    mma16816(acc[mi][ni], ah[mi], &bh[ni >> 1][(ni & 1) * 2]);
#pragma unroll
            for (int ni = 0; ni < 8; ++ni)
#pragma unroll
                for (int mi = 0; mi < 2; ++mi)
                    mma16816(acc[mi][ni], ah[mi], &bl[ni >> 1][(ni & 1) * 2]);
#pragma unroll
            for (int ni = 0; ni < 8; ++ni)
#pragma unroll
                for (int mi = 0; mi < 2; ++mi)
                    mma16816(acc[mi][ni], al[mi], &bh[ni >> 1][(ni & 1) * 2]);
        }
    }

    const int gid = lane >> 2, tig = lane & 3;
#pragma unroll
    for (int mi = 0; mi < 2; ++mi) {
#pragma unroll
        for (int ni = 0; ni < 8; ++ni) {
            const int row = m0 + wm + mi * 16 + gid;
            const int col = n0 + wn + ni * 8 + 2 * tig;
            *(float2*)&C[(size_t)row * N + col] =
                make_float2(acc[mi][ni][0], acc[mi][ni][1]);
            *(float2*)&C[(size_t)(row + 8) * N + col] =
                make_float2(acc[mi][ni][2], acc[mi][ni][3]);
        }
    }
}

// fused QKV projection: grid.x = 48 n-blocks (32 Q | 8 K | 8 V), grid.y = M/128
__global__ __launch_bounds__(256, 1)
void qkv_gemm(const __nv_bfloat16* __restrict__ hsh, const __nv_bfloat16* __restrict__ hsl,
              const __nv_bfloat16* __restrict__ wqh, const __nv_bfloat16* __restrict__ wql,
              const __nv_bfloat16* __restrict__ wkh, const __nv_bfloat16* __restrict__ wkl,
              const __nv_bfloat16* __restrict__ wvh, const __nv_bfloat16* __restrict__ wvl,
              float* __restrict__ q, float* __restrict__ kt, float* __restrict__ vt) {
    extern __shared__ char smc[];
    const uint32_t smb = smem_u32(smc);
    const int nb = blockIdx.x;
    const __nv_bfloat16 *Bh, *Bl;
    float* C;
    int N, n0;
    if (nb < 32)      { Bh = wqh; Bl = wql; C = q;  N = NH  * HD; n0 = nb * 128; }
    else if (nb < 40) { Bh = wkh; Bl = wkl; C = kt; N = NKV * HD; n0 = (nb - 32) * 128; }
    else              { Bh = wvh; Bl = wvl; C = vt; N = NKV * HD; n0 = (nb - 40) * 128; }
    gemm_core(smb, hsh, hsl, Bh, Bl, C, blockIdx.y * BM, n0, N, HID);
}

__global__ __launch_bounds__(256, 1)
void hgemm_nt(const __nv_bfloat16* __restrict__ Ahi, const __nv_bfloat16* __restrict__ Alo,
              const __nv_bfloat16* __restrict__ Bhi, const __nv_bfloat16* __restrict__ Blo,
              float* __restrict__ C, int N, int K) {
    extern __shared__ char smc[];
    gemm_core(smem_u32(smc), Ahi, Alo, Bhi, Blo, C,
              blockIdx.y * BM, blockIdx.x * BN, N, K);
}

// ---------------- flash attention (fp32, causal, GQA) ----------------
#define QPITCH 132
#define KPITCH 132
#define VPITCH 68
#define PPITCH 68
__global__ void attn_kernel(const float* __restrict__ Q, const float* __restrict__ K,
                            const float* __restrict__ V, float* __restrict__ O,
                            int S, float scale) {
    extern __shared__ float smf[];
    float* Qs = smf;
    float* Ks = Qs + 128 * QPITCH;
    float* Vt = Ks + 64 * KPITCH;
    float* Ps = Vt + 128 * VPITCH;

    int qt = blockIdx.x, h = blockIdx.y, b = blockIdx.z;
    int kvh = h / (NH / NKV);
    int tid = threadIdx.x;
    int tx = tid & 7, ty = tid >> 3;
    int q0 = qt * 128;

    for (int it = tid; it < 128 * 32; it += 256) {
        int r = it >> 5, dq = (it & 31) * 4;
        float4 v = *(const float4*)(Q + ((size_t)(b * S + q0 + r) * NH + h) * HD + dq);
        float* dst = &Qs[r * QPITCH + dq];
        dst[0] = v.x; dst[1] = v.y; dst[2] = v.z; dst[3] = v.w;
    }

    float m_i[4], l_i[4], Of[4][16];
#pragma unroll
    for (int i = 0; i < 4; ++i) {
        m_i[i] = -3.0e38f; l_i[i] = 0.f;
#pragma unroll
        for (int j = 0; j < 16; ++j) Of[i][j] = 0.f;
    }

    int ntiles = (q0 + 128) / 64;
    for (int t = 0; t < ntiles; ++t) {
        int kv0 = t * 64;
        __syncthreads();
        for (int it = tid; it < 64 * 32; it += 256) {
            int c = it >> 5, dq = (it & 31) * 4;
            const float* kp = K + ((size_t)(b * S + kv0 + c) * NKV + kvh) * HD + dq;
            float4 kk = *(const float4*)kp;
            float* kd = &Ks[c * KPITCH + dq];
            kd[0] = kk.x; kd[1] = kk.y; kd[2] = kk.z; kd[3] = kk.w;
            const float* vp = V + ((size_t)(b * S + kv0 + c) * NKV + kvh) * HD + dq;
            float4 vv = *(const float4*)vp;
            Vt[(dq + 0) * VPITCH + c] = vv.x;
            Vt[(dq + 1) * VPITCH + c] = vv.y;
            Vt[(dq + 2) * VPITCH + c] = vv.z;
            Vt[(dq + 3) * VPITCH + c] = vv.w;
        }
        __syncthreads();

        float acc[4][8];
#pragma unroll
        for (int i = 0; i < 4; ++i)
#pragma unroll
            for (int j = 0; j < 8; ++j) acc[i][j] = 0.f;
#pragma unroll 4
        for (int k4 = 0; k4 < 32; ++k4) {
            float4 qa[4];
#pragma unroll
            for (int i = 0; i < 4; ++i)
                qa[i] = *(const float4*)&Qs[(ty * 4 + i) * QPITCH + k4 * 4];
#pragma unroll
            for (int j = 0; j < 8; ++j) {
                float4 kb = *(const float4*)&Ks[(tx + 8 * j) * KPITCH + k4 * 4];
#pragma unroll
                for (int i = 0; i < 4; ++i)
                    acc[i][j] += qa[i].x * kb.x + qa[i].y * kb.y
                               + qa[i].z * kb.z + qa[i].w * kb.w;
            }
        }

#pragma unroll
        for (int i = 0; i < 4; ++i) {
            int qi = q0 + ty * 4 + i;
            float mrow = -3.0e38f;
#pragma unroll
            for (int j = 0; j < 8; ++j) {
                int kidx = kv0 + tx + 8 * j;
                float sv = (kidx <= qi) ? acc[i][j] * scale : -1.0e30f;
                acc[i][j] = sv;
                mrow = fmaxf(mrow, sv);
            }
            mrow = fmaxf(mrow, __shfl_xor_sync(0xffffffffu, mrow, 1));
            mrow = fmaxf(mrow, __shfl_xor_sync(0xffffffffu, mrow, 2));
            mrow = fmaxf(mrow, __shfl_xor_sync(0xffffffffu, mrow, 4));
            float mnew  = fmaxf(m_i[i], mrow);
            float alpha = expf(m_i[i] - mnew);
            float lsum = 0.f;
#pragma unroll
            for (int j = 0; j < 8; ++j) {
                float p = expf(acc[i][j] - mnew);
                acc[i][j] = p;
                lsum += p;
            }
            lsum += __shfl_xor_sync(0xffffffffu, lsum, 1);
            lsum += __shfl_xor_sync(0xffffffffu, lsum, 2);
            lsum += __shfl_xor_sync(0xffffffffu, lsum, 4);
            l_i[i] = l_i[i] * alpha + lsum;
            m_i[i] = mnew;
#pragma unroll
            for (int j = 0; j < 16; ++j) Of[i][j] *= alpha;
#pragma unroll
            for (int j = 0; j < 8; ++j)
                Ps[(ty * 4 + i) * PPITCH + tx + 8 * j] = acc[i][j];
        }
        __syncthreads();

#pragma unroll 4
        for (int k4 = 0; k4 < 16; ++k4) {
            float4 pa[4];
#pragma unroll
            for (int i = 0; i < 4; ++i)
                pa[i] = *(const float4*)&Ps[(ty * 4 + i) * PPITCH + k4 * 4];
#pragma unroll
            for (int j = 0; j < 16; ++j) {
                float4 vb = *(const float4*)&Vt[(tx + 8 * j) * VPITCH + k4 * 4];
#pragma unroll
                for (int i = 0; i < 4; ++i)
                    Of[i][j] += pa[i].x * vb.x + pa[i].y * vb.y
                              + pa[i].z * vb.z + pa[i].w * vb.w;
            }
        }
    }

#pragma unroll
    for (int i = 0; i < 4; ++i) {
        int row = q0 + ty * 4 + i;
        float inv = 1.f / l_i[i];
        float* op = O + ((size_t)(b * S + row) * NH + h) * HD;
#pragma unroll
        for (int j = 0; j < 16; ++j)
            op[tx + 8 * j] = Of[i][j] * inv;
    }
}

// ---------------- launch ----------------
extern "C" void kernel_launch(void* const* d_in, const int* in_sizes, int n_in,
                              void* d_out, int out_size) {
    const float* hs  = (const float*)d_in[0];
    const float* wq  = (const float*)d_in[1];
    const float* wk  = (const float*)d_in[2];
    const float* wv  = (const float*)d_in[3];
    const float* wo  = (const float*)d_in[4];
    const int*   pos = (const int*)  d_in[6];

    int nnz = in_sizes[0] / HID;
    int b   = in_sizes[10] - 1;
    int s   = nnz / b;

    float *q, *kt, *vt, *kg, *vg, *attn;
    cudaGetSymbolAddress((void**)&q,    g_q);
    cudaGetSymbolAddress((void**)&kt,   g_kt);
    cudaGetSymbolAddress((void**)&vt,   g_vt);
    cudaGetSymbolAddress((void**)&kg,   g_kg);
    cudaGetSymbolAddress((void**)&vg,   g_vg);
    cudaGetSymbolAddress((void**)&attn, g_attn);

    __nv_bfloat16 *hsh, *hsl, *wqh, *wql, *wkh, *wkl, *wvh, *wvl, *woh, *wol, *ath, *atl;
    cudaGetSymbolAddress((void**)&hsh, g_hs_hi);
    cudaGetSymbolAddress((void**)&hsl, g_hs_lo);
    cudaGetSymbolAddress((void**)&wqh, g_wq_hi);
    cudaGetSymbolAddress((void**)&wql, g_wq_lo);
    cudaGetSymbolAddress((void**)&wkh, g_wk_hi);
    cudaGetSymbolAddress((void**)&wkl, g_wk_lo);
    cudaGetSymbolAddress((void**)&wvh, g_wv_hi);
    cudaGetSymbolAddress((void**)&wvl, g_wv_lo);
    cudaGetSymbolAddress((void**)&woh, g_wo_hi);
    cudaGetSymbolAddress((void**)&wol, g_wo_lo);
    cudaGetSymbolAddress((void**)&ath, g_at_hi);
    cudaGetSymbolAddress((void**)&atl, g_at_lo);

    const size_t ATTN_SMEM =
        (size_t)(128 * QPITCH + 64 * KPITCH + 128 * VPITCH + 128 * PPITCH) * sizeof(float);
    cudaFuncSetAttribute(attn_kernel, cudaFuncAttributeMaxDynamicSharedMemorySize,
                         (int)ATTN_SMEM);
    cudaFuncSetAttribute(qkv_gemm, cudaFuncAttributeMaxDynamicSharedMemorySize, GEMM_SMEM);
    cudaFuncSetAttribute(hgemm_nt, cudaFuncAttributeMaxDynamicSharedMemorySize, GEMM_SMEM);

    // 1. RoPE cos/sin table
    rope_table_kernel<<<s, 64>>>();

    // 2. split-convert activations + weights to (bf16 hi, bf16 lo)
    {
        int n4;
        n4 = nnz * HID / 4;      cvt_split_kernel<<<(n4 + 255) / 256, 256>>>(hs, hsh, hsl, n4);
        n4 = NH  * HD * HID / 4; cvt_split_kernel<<<(n4 + 255) / 256, 256>>>(wq, wqh, wql, n4);
        n4 = NKV * HD * HID / 4; cvt_split_kernel<<<(n4 + 255) / 256, 256>>>(wk, wkh, wkl, n4);
        n4 = NKV * HD * HID / 4; cvt_split_kernel<<<(n4 + 255) / 256, 256>>>(wv, wvh, wvl, n4);
        n4 = HID * NH * HD / 4;  cvt_split_kernel<<<(n4 + 255) / 256, 256>>>(wo, woh, wol, n4);
    }

    // 3. fused Q/K/V projection (one launch, 48 n-blocks x nnz/128 m-blocks)
    qkv_gemm<<<dim3(48, nnz / BM), 256, GEMM_SMEM>>>(hsh, hsl, wqh, wql, wkh, wkl,
                                                     wvh, wvl, q, kt, vt);

    // 4. RoPE + paged-KV scatter (gathered order == position)
    rope_q_kernel<<<nnz, 256>>>(q, pos);
    ropekv_scatter_kernel<<<nnz, 256>>>(pos, s);

    // 5. causal GQA flash attention (fp32)
    float scale = 1.0f / sqrtf((float)HD);
    attn_kernel<<<dim3(s / 128, NH, b), 256, ATTN_SMEM>>>(q, kg, vg, attn, s, scale);

    // 6. output projection
    {
        int n4 = nnz * NH * HD / 4;
        cvt_split_kernel<<<(n4 + 255) / 256, 256>>>(attn, ath, atl, n4);
    }
    hgemm_nt<<<dim3(HID / BN, nnz / BM), 256, GEMM_SMEM>>>(ath, atl, woh, wol,
                                                           (float*)d_out, HID, NH * HD);
}

// round 12
// speedup vs baseline: 1.1188x; 1.1188x over previous
#include <cuda_runtime.h>
#include <cuda_bf16.h>
#include <math.h>
#include <stdint.h>

// ---------------- problem constants ----------------
#define HID 4096
#define NH  32
#define NKV 8
#define HD  128
#define MAX_NNZ 4096
#define MAX_S   1024

// ---------------- device scratch (no allocs allowed) ----------------
__device__ float g_q   [(size_t)MAX_NNZ * NH  * HD];
__device__ float g_kt  [(size_t)MAX_NNZ * NKV * HD];
__device__ float g_vt  [(size_t)MAX_NNZ * NKV * HD];
__device__ float g_kg  [(size_t)MAX_NNZ * NKV * HD];
__device__ float g_vg  [(size_t)MAX_NNZ * NKV * HD];
__device__ float g_attn[(size_t)MAX_NNZ * NH  * HD];
__device__ float g_cos [MAX_S * 64];
__device__ float g_sin [MAX_S * 64];

__device__ __nv_bfloat16 g_hs_hi[(size_t)MAX_NNZ * HID];
__device__ __nv_bfloat16 g_hs_lo[(size_t)MAX_NNZ * HID];
__device__ __nv_bfloat16 g_wq_hi[(size_t)NH  * HD * HID];
__device__ __nv_bfloat16 g_wq_lo[(size_t)NH  * HD * HID];
__device__ __nv_bfloat16 g_wk_hi[(size_t)NKV * HD * HID];
__device__ __nv_bfloat16 g_wk_lo[(size_t)NKV * HD * HID];
__device__ __nv_bfloat16 g_wv_hi[(size_t)NKV * HD * HID];
__device__ __nv_bfloat16 g_wv_lo[(size_t)NKV * HD * HID];
__device__ __nv_bfloat16 g_wo_hi[(size_t)HID * NH * HD];
__device__ __nv_bfloat16 g_wo_lo[(size_t)HID * NH * HD];
__device__ __nv_bfloat16 g_at_hi[(size_t)MAX_NNZ * NH * HD];
__device__ __nv_bfloat16 g_at_lo[(size_t)MAX_NNZ * NH * HD];

// ---------------- helpers ----------------
__device__ __forceinline__ uint32_t smem_u32(const void* p) {
    uint32_t a;
    asm("{ .reg .u64 t; cvta.to.shared.u64 t, %1; cvt.u32.u64 %0, t; }" : "=r"(a) : "l"(p));
    return a;
}
#define SWZ128(o) ((o) ^ (((o) >> 3) & 0x70))

__device__ __forceinline__ void mma16816(float* c, const uint32_t* a, const uint32_t* b) {
    asm volatile(
        "mma.sync.aligned.m16n8k16.row.col.f32.bf16.bf16.f32 "
        "{%0,%1,%2,%3}, {%4,%5,%6,%7}, {%8,%9}, {%0,%1,%2,%3};\n"
        : "+f"(c[0]), "+f"(c[1]), "+f"(c[2]), "+f"(c[3])
        : "r"(a[0]), "r"(a[1]), "r"(a[2]), "r"(a[3]), "r"(b[0]), "r"(b[1]));
}
__device__ __forceinline__ void ldsm4(uint32_t* r, uint32_t addr) {
    asm volatile("ldmatrix.sync.aligned.m8n8.x4.shared.b16 {%0,%1,%2,%3}, [%4];"
        : "=r"(r[0]), "=r"(r[1]), "=r"(r[2]), "=r"(r[3]) : "r"(addr));
}
__device__ __forceinline__ void cp16(uint32_t dst, const void* src) {
    asm volatile("cp.async.cg.shared.global [%0], [%1], 16;" :: "r"(dst), "l"(src));
}

// ---------------- fp32 -> (bf16 hi, bf16 lo) split ----------------
__global__ void cvt_split_kernel(const float* __restrict__ x,
                                 __nv_bfloat16* __restrict__ hi,
                                 __nv_bfloat16* __restrict__ lo, int n4) {
    int i = blockIdx.x * blockDim.x + threadIdx.x;
    if (i >= n4) return;
    float4 v = ((const float4*)x)[i];
    union { __nv_bfloat16 b[4]; uint2 u; } H, L;
    H.b[0] = __float2bfloat16_rn(v.x);
    H.b[1] = __float2bfloat16_rn(v.y);
    H.b[2] = __float2bfloat16_rn(v.z);
    H.b[3] = __float2bfloat16_rn(v.w);
    L.b[0] = __float2bfloat16_rn(v.x - __bfloat162float(H.b[0]));
    L.b[1] = __float2bfloat16_rn(v.y - __bfloat162float(H.b[1]));
    L.b[2] = __float2bfloat16_rn(v.z - __bfloat162float(H.b[2]));
    L.b[3] = __float2bfloat16_rn(v.w - __bfloat162float(H.b[3]));
    ((uint2*)hi)[i] = H.u;
    ((uint2*)lo)[i] = L.u;
}

// ---------------- RoPE table ----------------
__global__ void rope_table_kernel() {
    int p = blockIdx.x;
    int j = threadIdx.x;
    double e    = (double)j / 64.0;
    double freq = exp(-e * log(500000.0));
    const double PI = 3.14159265358979323846;
    double wavelen = 2.0 * PI / freq;
    double f;
    if (wavelen < 2048.0)       f = freq;
    else if (wavelen > 8192.0)  f = freq / 8.0;
    else {
        double smooth = (8192.0 / wavelen - 1.0) / 3.0;
        f = (1.0 - smooth) * freq / 8.0 + smooth * freq;
    }
    double ang = (double)p * f;
    g_cos[p * 64 + j] = (float)cos(ang);
    g_sin[p * 64 + j] = (float)sin(ang);
}

__global__ void rope_q_kernel(float* __restrict__ q, const int* __restrict__ pos) {
    int i = blockIdx.x;
    int p = pos[i];
    const float* cr = g_cos + (size_t)p * 64;
    const float* sr = g_sin + (size_t)p * 64;
    float* base = q + (size_t)i * (NH * HD);
    for (int idx = threadIdx.x; idx < NH * 64; idx += blockDim.x) {
        int h = idx >> 6, j = idx & 63;
        float c = cr[j], s = sr[j];
        float* hb = base + h * HD;
        float x1 = hb[j], x2 = hb[j + 64];
        hb[j]      = x1 * c - x2 * s;
        hb[j + 64] = x2 * c + x1 * s;
    }
}

__global__ void ropekv_scatter_kernel(const int* __restrict__ pos, int s_per_b) {
    int i = blockIdx.x;
    int b = i / s_per_b;
    int p = pos[i];
    int dst = b * s_per_b + p;
    const float* cr = g_cos + (size_t)p * 64;
    const float* sr = g_sin + (size_t)p * 64;
    const float* kin  = g_kt + (size_t)i   * (NKV * HD);
    float*       kout = g_kg + (size_t)dst * (NKV * HD);
    for (int idx = threadIdx.x; idx < NKV * 64; idx += blockDim.x) {
        int h = idx >> 6, j = idx & 63;
        float c = cr[j], s = sr[j];
        float x1 = kin[h * HD + j], x2 = kin[h * HD + j + 64];
        kout[h * HD + j]      = x1 * c - x2 * s;
        kout[h * HD + j + 64] = x2 * c + x1 * s;
    }
    const float* vin  = g_vt + (size_t)i   * (NKV * HD);
    float*       vout = g_vg + (size_t)dst * (NKV * HD);
    for (int idx = threadIdx.x; idx < NKV * HD; idx += blockDim.x)
        vout[idx] = vin[idx];
}

// ================= HMMA split-bf16 GEMM core (R10 shape + 3 stages) =========
// C tile at (m0,n0) = A[M,K] * B[N,K]^T via 3xBF16 (hh + hl + lh).
// BM=BN=128, BK=64. 256 threads = 8 warps (4m x 2n), warp tile 32x64.
// 3-stage cp.async pipeline, SW128 smem, ldmatrix fragment loads.
#define BM 128
#define BN 128
#define BK 64
#define NSTAGE   3
#define ST_BYTES (64 * 1024)
#define OFF_AH   0
#define OFF_AL   (16 * 1024)
#define OFF_BH   (32 * 1024)
#define OFF_BL   (48 * 1024)
#define GEMM_SMEM (NSTAGE * ST_BYTES)

__device__ __forceinline__ void load_stage(
    uint32_t sb, int tid,
    const __nv_bfloat16* __restrict__ Ahi, const __nv_bfloat16* __restrict__ Alo,
    const __nv_bfloat16* __restrict__ Bhi, const __nv_bfloat16* __restrict__ Blo,
    int m0, int n0, int K, int k0) {
#pragma unroll
    for (int i = 0; i < 4; ++i) {
        int idx = tid + i * 256;              // 0..1023: 128 rows x 8 chunks(16B)
        int r = idx >> 3, c = idx & 7;
        uint32_t off = SWZ128((uint32_t)(r * 128 + c * 16));
        const size_t ga = (size_t)(m0 + r) * K + k0 + c * 8;
        cp16(sb + OFF_AH + off, Ahi + ga);
        cp16(sb + OFF_AL + off, Alo + ga);
        const size_t gb = (size_t)(n0 + r) * K + k0 + c * 8;
        cp16(sb + OFF_BH + off, Bhi + gb);
        cp16(sb + OFF_BL + off, Blo + gb);
    }
    asm volatile("cp.async.commit_group;" ::: "memory");
}

__device__ __forceinline__ void gemm_core(
    uint32_t smb,
    const __nv_bfloat16* __restrict__ Ahi, const __nv_bfloat16* __restrict__ Alo,
    const __nv_bfloat16* __restrict__ Bhi, const __nv_bfloat16* __restrict__ Blo,
    float* __restrict__ C, int m0, int n0, int N, int K) {
    const int tid  = threadIdx.x;
    const int wid  = tid >> 5;
    const int lane = tid & 31;
    const int wm = (wid & 3) << 5;    // 0,32,64,96
    const int wn = (wid >> 2) << 6;   // 0,64

    const int a_row0 = wm + (lane & 15);
    const int a_csel = lane >> 4;
    const int b_row0 = wn + (lane & 7) + ((lane >> 4) << 3);
    const int b_csel = (lane >> 3) & 1;

    float acc[2][8][4];
#pragma unroll
    for (int mi = 0; mi < 2; ++mi)
#pragma unroll
        for (int ni = 0; ni < 8; ++ni)
#pragma unroll
            for (int r = 0; r < 4; ++r) acc[mi][ni][r] = 0.f;

    const int NIT = K / BK;

    // prologue: fill NSTAGE-1 stages
    load_stage(smb + 0 * ST_BYTES, tid, Ahi, Alo, Bhi, Blo, m0, n0, K, 0);
    if (NIT > 1)
        load_stage(smb + 1 * ST_BYTES, tid, Ahi, Alo, Bhi, Blo, m0, n0, K, BK);

    int buf = 0;
    for (int it = 0; it < NIT; ++it) {
        // stage `it` complete; keep at most 1 group (stage it+1) in flight
        if (it + 1 < NIT) asm volatile("cp.async.wait_group 1;" ::: "memory");
        else              asm volatile("cp.async.wait_group 0;" ::: "memory");
        __syncthreads();  // also: all warps finished compute of it-1 => buffer (it+2)%3 free

        if (it + 2 < NIT) {
            int nb = buf + 2; if (nb >= NSTAGE) nb -= NSTAGE;
            load_stage(smb + nb * ST_BYTES, tid, Ahi, Alo, Bhi, Blo, m0, n0, K, (it + 2) * BK);
        }

        const uint32_t sb = smb + buf * ST_BYTES;
#pragma unroll
        for (int ks = 0; ks < 4; ++ks) {
            const int kc = ks * 2;
            uint32_t ah[2][4], al[2][4], bh[4][4], bl[4][4];
#pragma unroll
            for (int mi = 0; mi < 2; ++mi) {
                uint32_t off = SWZ128((uint32_t)((a_row0 + mi * 16) * 128 + (kc + a_csel) * 16));
                ldsm4(ah[mi], sb + OFF_AH + off);
                ldsm4(al[mi], sb + OFF_AL + off);
            }
#pragma unroll
            for (int ni2 = 0; ni2 < 4; ++ni2) {
                uint32_t off = SWZ128((uint32_t)((b_row0 + ni2 * 16) * 128 + (kc + b_csel) * 16));
                ldsm4(bh[ni2], sb + OFF_BH + off);
                ldsm4(bl[ni2], sb + OFF_BL + off);
            }
#pragma unroll
            for (int ni = 0; ni < 8; ++ni)
#pragma unroll
                for (int mi = 0; mi < 2; ++mi)
                    mma16816(acc[mi][ni], ah[mi], &bh[ni >> 1][(ni & 1) * 2]);
#pragma unroll
            for (int ni = 0; ni < 8; ++ni)
#pragma unroll
                for (int mi = 0; mi < 2; ++mi)
                    mma16816(acc[mi][ni], ah[mi], &bl[ni >> 1][(ni & 1) * 2]);
#pragma unroll
            for (int ni = 0; ni < 8; ++ni)
#pragma unroll
                for (int mi = 0; mi < 2; ++mi)
                    mma16816(acc[mi][ni], al[mi], &bh[ni >> 1][(ni & 1) * 2]);
        }
        if (++buf == NSTAGE) buf = 0;
    }

    const int gid = lane >> 2, tig = lane & 3;
#pragma unroll
    for (int mi = 0; mi < 2; ++mi) {
#pragma unroll
        for (int ni = 0; ni < 8; ++ni) {
            const int row = m0 + wm + mi * 16 + gid;
            const int col = n0 + wn + ni * 8 + 2 * tig;
            *(float2*)&C[(size_t)row * N + col] =
                make_float2(acc[mi][ni][0], acc[mi][ni][1]);
            *(float2*)&C[(size_t)(row + 8) * N + col] =
                make_float2(acc[mi][ni][2], acc[mi][ni][3]);
        }
    }
}

// fused QKV projection: grid.x = 48 n-blocks (32 Q | 8 K | 8 V), grid.y = M/128
__global__ __launch_bounds__(256, 1)
void qkv_gemm(const __nv_bfloat16* __restrict__ hsh, const __nv_bfloat16* __restrict__ hsl,
              const __nv_bfloat16* __restrict__ wqh, const __nv_bfloat16* __restrict__ wql,
              const __nv_bfloat16* __restrict__ wkh, const __nv_bfloat16* __restrict__ wkl,
              const __nv_bfloat16* __restrict__ wvh, const __nv_bfloat16* __restrict__ wvl,
              float* __restrict__ q, float* __restrict__ kt, float* __restrict__ vt) {
    extern __shared__ char smc[];
    const uint32_t smb = smem_u32(smc);
    const int nb = blockIdx.x;
    const __nv_bfloat16 *Bh, *Bl;
    float* C;
    int N, n0;
    if (nb < 32)      { Bh = wqh; Bl = wql; C = q;  N = NH  * HD; n0 = nb * 128; }
    else if (nb < 40) { Bh = wkh; Bl = wkl; C = kt; N = NKV * HD; n0 = (nb - 32) * 128; }
    else              { Bh = wvh; Bl = wvl; C = vt; N = NKV * HD; n0 = (nb - 40) * 128; }
    gemm_core(smb, hsh, hsl, Bh, Bl, C, blockIdx.y * BM, n0, N, HID);
}

__global__ __launch_bounds__(256, 1)
void hgemm_nt(const __nv_bfloat16* __restrict__ Ahi, const __nv_bfloat16* __restrict__ Alo,
              const __nv_bfloat16* __restrict__ Bhi, const __nv_bfloat16* __restrict__ Blo,
              float* __restrict__ C, int N, int K) {
    extern __shared__ char smc[];
    gemm_core(smem_u32(smc), Ahi, Alo, Bhi, Blo, C,
              blockIdx.y * BM, blockIdx.x * BN, N, K);
}

// ---------------- flash attention (fp32, causal, GQA) ----------------
#define QPITCH 132
#define KPITCH 132
#define VPITCH 68
#define PPITCH 68
__global__ void attn_kernel(const float* __restrict__ Q, const float* __restrict__ K,
                            const float* __restrict__ V, float* __restrict__ O,
                            int S, float scale) {
    extern __shared__ float smf[];
    float* Qs = smf;
    float* Ks = Qs + 128 * QPITCH;
    float* Vt = Ks + 64 * KPITCH;
    float* Ps = Vt + 128 * VPITCH;

    int qt = blockIdx.x, h = blockIdx.y, b = blockIdx.z;
    int kvh = h / (NH / NKV);
    int tid = threadIdx.x;
    int tx = tid & 7, ty = tid >> 3;
    int q0 = qt * 128;

    for (int it = tid; it < 128 * 32; it += 256) {
        int r = it >> 5, dq = (it & 31) * 4;
        float4 v = *(const float4*)(Q + ((size_t)(b * S + q0 + r) * NH + h) * HD + dq);
        float* dst = &Qs[r * QPITCH + dq];
        dst[0] = v.x; dst[1] = v.y; dst[2] = v.z; dst[3] = v.w;
    }

    float m_i[4], l_i[4], Of[4][16];
#pragma unroll
    for (int i = 0; i < 4; ++i) {
        m_i[i] = -3.0e38f; l_i[i] = 0.f;
#pragma unroll
        for (int j = 0; j < 16; ++j) Of[i][j] = 0.f;
    }

    int ntiles = (q0 + 128) / 64;
    for (int t = 0; t < ntiles; ++t) {
        int kv0 = t * 64;
        __syncthreads();
        for (int it = tid; it < 64 * 32; it += 256) {
            int c = it >> 5, dq = (it & 31) * 4;
            const float* kp = K + ((size_t)(b * S + kv0 + c) * NKV + kvh) * HD + dq;
            float4 kk = *(const float4*)kp;
            float* kd = &Ks[c * KPITCH + dq];
            kd[0] = kk.x; kd[1] = kk.y; kd[2] = kk.z; kd[3] = kk.w;
            const float* vp = V + ((size_t)(b * S + kv0 + c) * NKV + kvh) * HD + dq;
            float4 vv = *(const float4*)vp;
            Vt[(dq + 0) * VPITCH + c] = vv.x;
            Vt[(dq + 1) * VPITCH + c] = vv.y;
            Vt[(dq + 2) * VPITCH + c] = vv.z;
            Vt[(dq + 3) * VPITCH + c] = vv.w;
        }
        __syncthreads();

        float acc[4][8];
#pragma unroll
        for (int i = 0; i < 4; ++i)
#pragma unroll
            for (int j = 0; j < 8; ++j) acc[i][j] = 0.f;
#pragma unroll 4
        for (int k4 = 0; k4 < 32; ++k4) {
            float4 qa[4];
#pragma unroll
            for (int i = 0; i < 4; ++i)
                qa[i] = *(const float4*)&Qs[(ty * 4 + i) * QPITCH + k4 * 4];
#pragma unroll
            for (int j = 0; j < 8; ++j) {
                float4 kb = *(const float4*)&Ks[(tx + 8 * j) * KPITCH + k4 * 4];
#pragma unroll
                for (int i = 0; i < 4; ++i)
                    acc[i][j] += qa[i].x * kb.x + qa[i].y * kb.y
                               + qa[i].z * kb.z + qa[i].w * kb.w;
            }
        }

#pragma unroll
        for (int i = 0; i < 4; ++i) {
            int qi = q0 + ty * 4 + i;
            float mrow = -3.0e38f;
#pragma unroll
            for (int j = 0; j < 8; ++j) {
                int kidx = kv0 + tx + 8 * j;
                float sv = (kidx <= qi) ? acc[i][j] * scale : -1.0e30f;
                acc[i][j] = sv;
                mrow = fmaxf(mrow, sv);
            }
            mrow = fmaxf(mrow, __shfl_xor_sync(0xffffffffu, mrow, 1));
            mrow = fmaxf(mrow, __shfl_xor_sync(0xffffffffu, mrow, 2));
            mrow = fmaxf(mrow, __shfl_xor_sync(0xffffffffu, mrow, 4));
            float mnew  = fmaxf(m_i[i], mrow);
            float alpha = expf(m_i[i] - mnew);
            float lsum = 0.f;
#pragma unroll
            for (int j = 0; j < 8; ++j) {
                float p = expf(acc[i][j] - mnew);
                acc[i][j] = p;
                lsum += p;
            }
            lsum += __shfl_xor_sync(0xffffffffu, lsum, 1);
            lsum += __shfl_xor_sync(0xffffffffu, lsum, 2);
            lsum += __shfl_xor_sync(0xffffffffu, lsum, 4);
            l_i[i] = l_i[i] * alpha + lsum;
            m_i[i] = mnew;
#pragma unroll
            for (int j = 0; j < 16; ++j) Of[i][j] *= alpha;
#pragma unroll
            for (int j = 0; j < 8; ++j)
                Ps[(ty * 4 + i) * PPITCH + tx + 8 * j] = acc[i][j];
        }
        __syncthreads();

#pragma unroll 4
        for (int k4 = 0; k4 < 16; ++k4) {
            float4 pa[4];
#pragma unroll
            for (int i = 0; i < 4; ++i)
                pa[i] = *(const float4*)&Ps[(ty * 4 + i) * PPITCH + k4 * 4];
#pragma unroll
            for (int j = 0; j < 16; ++j) {
                float4 vb = *(const float4*)&Vt[(tx + 8 * j) * VPITCH + k4 * 4];
#pragma unroll
                for (int i = 0; i < 4; ++i)
                    Of[i][j] += pa[i].x * vb.x + pa[i].y * vb.y
                              + pa[i].z * vb.z + pa[i].w * vb.w;
            }
        }
    }

#pragma unroll
    for (int i = 0; i < 4; ++i) {
        int row = q0 + ty * 4 + i;
        float inv = 1.f / l_i[i];
        float* op = O + ((size_t)(b * S + row) * NH + h) * HD;
#pragma unroll
        for (int j = 0; j < 16; ++j)
            op[tx + 8 * j] = Of[i][j] * inv;
    }
}

// ---------------- launch ----------------
extern "C" void kernel_launch(void* const* d_in, const int* in_sizes, int n_in,
                              void* d_out, int out_size) {
    const float* hs  = (const float*)d_in[0];
    const float* wq  = (const float*)d_in[1];
    const float* wk  = (const float*)d_in[2];
    const float* wv  = (const float*)d_in[3];
    const float* wo  = (const float*)d_in[4];
    const int*   pos = (const int*)  d_in[6];

    int nnz = in_sizes[0] / HID;
    int b   = in_sizes[10] - 1;
    int s   = nnz / b;

    float *q, *kt, *vt, *kg, *vg, *attn;
    cudaGetSymbolAddress((void**)&q,    g_q);
    cudaGetSymbolAddress((void**)&kt,   g_kt);
    cudaGetSymbolAddress((void**)&vt,   g_vt);
    cudaGetSymbolAddress((void**)&kg,   g_kg);
    cudaGetSymbolAddress((void**)&vg,   g_vg);
    cudaGetSymbolAddress((void**)&attn, g_attn);

    __nv_bfloat16 *hsh, *hsl, *wqh, *wql, *wkh, *wkl, *wvh, *wvl, *woh, *wol, *ath, *atl;
    cudaGetSymbolAddress((void**)&hsh, g_hs_hi);
    cudaGetSymbolAddress((void**)&hsl, g_hs_lo);
    cudaGetSymbolAddress((void**)&wqh, g_wq_hi);
    cudaGetSymbolAddress((void**)&wql, g_wq_lo);
    cudaGetSymbolAddress((void**)&wkh, g_wk_hi);
    cudaGetSymbolAddress((void**)&wkl, g_wk_lo);
    cudaGetSymbolAddress((void**)&wvh, g_wv_hi);
    cudaGetSymbolAddress((void**)&wvl, g_wv_lo);
    cudaGetSymbolAddress((void**)&woh, g_wo_hi);
    cudaGetSymbolAddress((void**)&wol, g_wo_lo);
    cudaGetSymbolAddress((void**)&ath, g_at_hi);
    cudaGetSymbolAddress((void**)&atl, g_at_lo);

    const size_t ATTN_SMEM =
        (size_t)(128 * QPITCH + 64 * KPITCH + 128 * VPITCH + 128 * PPITCH) * sizeof(float);
    cudaFuncSetAttribute(attn_kernel, cudaFuncAttributeMaxDynamicSharedMemorySize,
                         (int)ATTN_SMEM);
    cudaFuncSetAttribute(qkv_gemm, cudaFuncAttributeMaxDynamicSharedMemorySize, GEMM_SMEM);
    cudaFuncSetAttribute(hgemm_nt, cudaFuncAttributeMaxDynamicSharedMemorySize, GEMM_SMEM);

    // 1. RoPE cos/sin table
    rope_table_kernel<<<s, 64>>>();

    // 2. split-convert activations + weights to (bf16 hi, bf16 lo)
    {
        int n4;
        n4 = nnz * HID / 4;      cvt_split_kernel<<<(n4 + 255) / 256, 256>>>(hs, hsh, hsl, n4);
        n4 = NH  * HD * HID / 4; cvt_split_kernel<<<(n4 + 255) / 256, 256>>>(wq, wqh, wql, n4);
        n4 = NKV * HD * HID / 4; cvt_split_kernel<<<(n4 + 255) / 256, 256>>>(wk, wkh, wkl, n4);
        n4 = NKV * HD * HID / 4; cvt_split_kernel<<<(n4 + 255) / 256, 256>>>(wv, wvh, wvl, n4);
        n4 = HID * NH * HD / 4;  cvt_split_kernel<<<(n4 + 255) / 256, 256>>>(wo, woh, wol, n4);
    }

    // 3. fused Q/K/V projection (one launch, 48 n-blocks x nnz/128 m-blocks)
    qkv_gemm<<<dim3(48, nnz / BM), 256, GEMM_SMEM>>>(hsh, hsl, wqh, wql, wkh, wkl,
                                                     wvh, wvl, q, kt, vt);

    // 4. RoPE + paged-KV scatter (gathered order == position)
    rope_q_kernel<<<nnz, 256>>>(q, pos);
    ropekv_scatter_kernel<<<nnz, 256>>>(pos, s);

    // 5. causal GQA flash attention (fp32)
    float scale = 1.0f / sqrtf((float)HD);
    attn_kernel<<<dim3(s / 128, NH, b), 256, ATTN_SMEM>>>(q, kg, vg, attn, s, scale);

    // 6. output projection
    {
        int n4 = nnz * NH * HD / 4;
        cvt_split_kernel<<<(n4 + 255) / 256, 256>>>(attn, ath, atl, n4);
    }
    hgemm_nt<<<dim3(HID / BN, nnz / BM), 256, GEMM_SMEM>>>(ath, atl, woh, wol,
                                                           (float*)d_out, HID, NH * HD);
}

// round 13
// speedup vs baseline: 1.1973x; 1.0701x over previous
#include <cuda_runtime.h>
#include <cuda_bf16.h>
#include <cuda_fp16.h>
#include <math.h>
#include <stdint.h>

// ---------------- problem constants ----------------
#define HID 4096
#define NH  32
#define NKV 8
#define HD  128
#define MAX_NNZ 4096
#define MAX_S   1024

// ---------------- device scratch (no allocs allowed) ----------------
__device__ float g_q   [(size_t)MAX_NNZ * NH  * HD];
__device__ float g_kt  [(size_t)MAX_NNZ * NKV * HD];
__device__ float g_vt  [(size_t)MAX_NNZ * NKV * HD];
__device__ float g_kg  [(size_t)MAX_NNZ * NKV * HD];
__device__ float g_vg  [(size_t)MAX_NNZ * NKV * HD];
__device__ float g_attn[(size_t)MAX_NNZ * NH  * HD];
__device__ float g_cos [MAX_S * 64];
__device__ float g_sin [MAX_S * 64];

__device__ __nv_bfloat16 g_hs_hi[(size_t)MAX_NNZ * HID];
__device__ __nv_bfloat16 g_hs_lo[(size_t)MAX_NNZ * HID];
__device__ __nv_bfloat16 g_wq_hi[(size_t)NH  * HD * HID];
__device__ __nv_bfloat16 g_wq_lo[(size_t)NH  * HD * HID];
__device__ __nv_bfloat16 g_wk_hi[(size_t)NKV * HD * HID];
__device__ __nv_bfloat16 g_wk_lo[(size_t)NKV * HD * HID];
__device__ __nv_bfloat16 g_wv_hi[(size_t)NKV * HD * HID];
__device__ __nv_bfloat16 g_wv_lo[(size_t)NKV * HD * HID];
// O-projection operands: fp16, A split 2-term, B rounded once
__device__ __half g_wo_h [(size_t)HID * NH * HD];
__device__ __half g_at_hi[(size_t)MAX_NNZ * NH * HD];
__device__ __half g_at_lo[(size_t)MAX_NNZ * NH * HD];

// ---------------- helpers ----------------
__device__ __forceinline__ uint32_t smem_u32(const void* p) {
    uint32_t a;
    asm("{ .reg .u64 t; cvta.to.shared.u64 t, %1; cvt.u32.u64 %0, t; }" : "=r"(a) : "l"(p));
    return a;
}
#define SWZ128(o) ((o) ^ (((o) >> 3) & 0x70))

__device__ __forceinline__ void mma16816(float* c, const uint32_t* a, const uint32_t* b) {
    asm volatile(
        "mma.sync.aligned.m16n8k16.row.col.f32.bf16.bf16.f32 "
        "{%0,%1,%2,%3}, {%4,%5,%6,%7}, {%8,%9}, {%0,%1,%2,%3};\n"
        : "+f"(c[0]), "+f"(c[1]), "+f"(c[2]), "+f"(c[3])
        : "r"(a[0]), "r"(a[1]), "r"(a[2]), "r"(a[3]), "r"(b[0]), "r"(b[1]));
}
__device__ __forceinline__ void mma16816h(float* c, const uint32_t* a, const uint32_t* b) {
    asm volatile(
        "mma.sync.aligned.m16n8k16.row.col.f32.f16.f16.f32 "
        "{%0,%1,%2,%3}, {%4,%5,%6,%7}, {%8,%9}, {%0,%1,%2,%3};\n"
        : "+f"(c[0]), "+f"(c[1]), "+f"(c[2]), "+f"(c[3])
        : "r"(a[0]), "r"(a[1]), "r"(a[2]), "r"(a[3]), "r"(b[0]), "r"(b[1]));
}
__device__ __forceinline__ void ldsm4(uint32_t* r, uint32_t addr) {
    asm volatile("ldmatrix.sync.aligned.m8n8.x4.shared.b16 {%0,%1,%2,%3}, [%4];"
        : "=r"(r[0]), "=r"(r[1]), "=r"(r[2]), "=r"(r[3]) : "r"(addr));
}
__device__ __forceinline__ void cp16(uint32_t dst, const void* src) {
    asm volatile("cp.async.cg.shared.global [%0], [%1], 16;" :: "r"(dst), "l"(src));
}

// ---------------- fp32 -> (bf16 hi, bf16 lo) split ----------------
__global__ void cvt_split_kernel(const float* __restrict__ x,
                                 __nv_bfloat16* __restrict__ hi,
                                 __nv_bfloat16* __restrict__ lo, int n4) {
    int i = blockIdx.x * blockDim.x + threadIdx.x;
    if (i >= n4) return;
    float4 v = ((const float4*)x)[i];
    union { __nv_bfloat16 b[4]; uint2 u; } H, L;
    H.b[0] = __float2bfloat16_rn(v.x);
    H.b[1] = __float2bfloat16_rn(v.y);
    H.b[2] = __float2bfloat16_rn(v.z);
    H.b[3] = __float2bfloat16_rn(v.w);
    L.b[0] = __float2bfloat16_rn(v.x - __bfloat162float(H.b[0]));
    L.b[1] = __float2bfloat16_rn(v.y - __bfloat162float(H.b[1]));
    L.b[2] = __float2bfloat16_rn(v.z - __bfloat162float(H.b[2]));
    L.b[3] = __float2bfloat16_rn(v.w - __bfloat162float(H.b[3]));
    ((uint2*)hi)[i] = H.u;
    ((uint2*)lo)[i] = L.u;
}

// ---------------- fp32 -> (fp16 hi, fp16 lo) split ----------------
__global__ void cvt_split_f16_kernel(const float* __restrict__ x,
                                     __half* __restrict__ hi,
                                     __half* __restrict__ lo, int n4) {
    int i = blockIdx.x * blockDim.x + threadIdx.x;
    if (i >= n4) return;
    float4 v = ((const float4*)x)[i];
    union { __half h[4]; uint2 u; } H, L;
    H.h[0] = __float2half_rn(v.x);
    H.h[1] = __float2half_rn(v.y);
    H.h[2] = __float2half_rn(v.z);
    H.h[3] = __float2half_rn(v.w);
    L.h[0] = __float2half_rn(v.x - __half2float(H.h[0]));
    L.h[1] = __float2half_rn(v.y - __half2float(H.h[1]));
    L.h[2] = __float2half_rn(v.z - __half2float(H.h[2]));
    L.h[3] = __float2half_rn(v.w - __half2float(H.h[3]));
    ((uint2*)hi)[i] = H.u;
    ((uint2*)lo)[i] = L.u;
}

// ---------------- fp32 -> fp16 round ----------------
__global__ void cvt_f16_kernel(const float* __restrict__ x,
                               __half* __restrict__ h, int n4) {
    int i = blockIdx.x * blockDim.x + threadIdx.x;
    if (i >= n4) return;
    float4 v = ((const float4*)x)[i];
    union { __half h[4]; uint2 u; } H;
    H.h[0] = __float2half_rn(v.x);
    H.h[1] = __float2half_rn(v.y);
    H.h[2] = __float2half_rn(v.z);
    H.h[3] = __float2half_rn(v.w);
    ((uint2*)h)[i] = H.u;
}

// ---------------- RoPE table ----------------
__global__ void rope_table_kernel() {
    int p = blockIdx.x;
    int j = threadIdx.x;
    double e    = (double)j / 64.0;
    double freq = exp(-e * log(500000.0));
    const double PI = 3.14159265358979323846;
    double wavelen = 2.0 * PI / freq;
    double f;
    if (wavelen < 2048.0)       f = freq;
    else if (wavelen > 8192.0)  f = freq / 8.0;
    else {
        double smooth = (8192.0 / wavelen - 1.0) / 3.0;
        f = (1.0 - smooth) * freq / 8.0 + smooth * freq;
    }
    double ang = (double)p * f;
    g_cos[p * 64 + j] = (float)cos(ang);
    g_sin[p * 64 + j] = (float)sin(ang);
}

__global__ void rope_q_kernel(float* __restrict__ q, const int* __restrict__ pos) {
    int i = blockIdx.x;
    int p = pos[i];
    const float* cr = g_cos + (size_t)p * 64;
    const float* sr = g_sin + (size_t)p * 64;
    float* base = q + (size_t)i * (NH * HD);
    for (int idx = threadIdx.x; idx < NH * 64; idx += blockDim.x) {
        int h = idx >> 6, j = idx & 63;
        float c = cr[j], s = sr[j];
        float* hb = base + h * HD;
        float x1 = hb[j], x2 = hb[j + 64];
        hb[j]      = x1 * c - x2 * s;
        hb[j + 64] = x2 * c + x1 * s;
    }
}

__global__ void ropekv_scatter_kernel(const int* __restrict__ pos, int s_per_b) {
    int i = blockIdx.x;
    int b = i / s_per_b;
    int p = pos[i];
    int dst = b * s_per_b + p;
    const float* cr = g_cos + (size_t)p * 64;
    const float* sr = g_sin + (size_t)p * 64;
    const float* kin  = g_kt + (size_t)i   * (NKV * HD);
    float*       kout = g_kg + (size_t)dst * (NKV * HD);
    for (int idx = threadIdx.x; idx < NKV * 64; idx += blockDim.x) {
        int h = idx >> 6, j = idx & 63;
        float c = cr[j], s = sr[j];
        float x1 = kin[h * HD + j], x2 = kin[h * HD + j + 64];
        kout[h * HD + j]      = x1 * c - x2 * s;
        kout[h * HD + j + 64] = x2 * c + x1 * s;
    }
    const float* vin  = g_vt + (size_t)i   * (NKV * HD);
    float*       vout = g_vg + (size_t)dst * (NKV * HD);
    for (int idx = threadIdx.x; idx < NKV * HD; idx += blockDim.x)
        vout[idx] = vin[idx];
}

// ================= 3xBF16 HMMA GEMM core (QKV projections) =================
#define BM 128
#define BN 128
#define BK 64
#define NSTAGE   3
#define ST_BYTES (64 * 1024)
#define OFF_AH   0
#define OFF_AL   (16 * 1024)
#define OFF_BH   (32 * 1024)
#define OFF_BL   (48 * 1024)
#define GEMM_SMEM (NSTAGE * ST_BYTES)

__device__ __forceinline__ void load_stage(
    uint32_t sb, int tid,
    const __nv_bfloat16* __restrict__ Ahi, const __nv_bfloat16* __restrict__ Alo,
    const __nv_bfloat16* __restrict__ Bhi, const __nv_bfloat16* __restrict__ Blo,
    int m0, int n0, int K, int k0) {
#pragma unroll
    for (int i = 0; i < 4; ++i) {
        int idx = tid + i * 256;
        int r = idx >> 3, c = idx & 7;
        uint32_t off = SWZ128((uint32_t)(r * 128 + c * 16));
        const size_t ga = (size_t)(m0 + r) * K + k0 + c * 8;
        cp16(sb + OFF_AH + off, Ahi + ga);
        cp16(sb + OFF_AL + off, Alo + ga);
        const size_t gb = (size_t)(n0 + r) * K + k0 + c * 8;
        cp16(sb + OFF_BH + off, Bhi + gb);
        cp16(sb + OFF_BL + off, Blo + gb);
    }
    asm volatile("cp.async.commit_group;" ::: "memory");
}

__device__ __forceinline__ void gemm_core(
    uint32_t smb,
    const __nv_bfloat16* __restrict__ Ahi, const __nv_bfloat16* __restrict__ Alo,
    const __nv_bfloat16* __restrict__ Bhi, const __nv_bfloat16* __restrict__ Blo,
    float* __restrict__ C, int m0, int n0, int N, int K) {
    const int tid  = threadIdx.x;
    const int wid  = tid >> 5;
    const int lane = tid & 31;
    const int wm = (wid & 3) << 5;
    const int wn = (wid >> 2) << 6;

    const int a_row0 = wm + (lane & 15);
    const int a_csel = lane >> 4;
    const int b_row0 = wn + (lane & 7) + ((lane >> 4) << 3);
    const int b_csel = (lane >> 3) & 1;

    float acc[2][8][4];
#pragma unroll
    for (int mi = 0; mi < 2; ++mi)
#pragma unroll
        for (int ni = 0; ni < 8; ++ni)
#pragma unroll
            for (int r = 0; r < 4; ++r) acc[mi][ni][r] = 0.f;

    const int NIT = K / BK;
    load_stage(smb + 0 * ST_BYTES, tid, Ahi, Alo, Bhi, Blo, m0, n0, K, 0);
    if (NIT > 1)
        load_stage(smb + 1 * ST_BYTES, tid, Ahi, Alo, Bhi, Blo, m0, n0, K, BK);

    int buf = 0;
    for (int it = 0; it < NIT; ++it) {
        if (it + 1 < NIT) asm volatile("cp.async.wait_group 1;" ::: "memory");
        else              asm volatile("cp.async.wait_group 0;" ::: "memory");
        __syncthreads();

        if (it + 2 < NIT) {
            int nb = buf + 2; if (nb >= NSTAGE) nb -= NSTAGE;
            load_stage(smb + nb * ST_BYTES, tid, Ahi, Alo, Bhi, Blo, m0, n0, K, (it + 2) * BK);
        }

        const uint32_t sb = smb + buf * ST_BYTES;
#pragma unroll
        for (int ks = 0; ks < 4; ++ks) {
            const int kc = ks * 2;
            uint32_t ah[2][4], al[2][4], bh[4][4], bl[4][4];
#pragma unroll
            for (int mi = 0; mi < 2; ++mi) {
                uint32_t off = SWZ128((uint32_t)((a_row0 + mi * 16) * 128 + (kc + a_csel) * 16));
                ldsm4(ah[mi], sb + OFF_AH + off);
                ldsm4(al[mi], sb + OFF_AL + off);
            }
#pragma unroll
            for (int ni2 = 0; ni2 < 4; ++ni2) {
                uint32_t off = SWZ128((uint32_t)((b_row0 + ni2 * 16) * 128 + (kc + b_csel) * 16));
                ldsm4(bh[ni2], sb + OFF_BH + off);
                ldsm4(bl[ni2], sb + OFF_BL + off);
            }
#pragma unroll
            for (int ni = 0; ni < 8; ++ni)
#pragma unroll
                for (int mi = 0; mi < 2; ++mi)
                    mma16816(acc[mi][ni], ah[mi], &bh[ni >> 1][(ni & 1) * 2]);
#pragma unroll
            for (int ni = 0; ni < 8; ++ni)
#pragma unroll
                for (int mi = 0; mi < 2; ++mi)
                    mma16816(acc[mi][ni], ah[mi], &bl[ni >> 1][(ni & 1) * 2]);
#pragma unroll
            for (int ni = 0; ni < 8; ++ni)
#pragma unroll
                for (int mi = 0; mi < 2; ++mi)
                    mma16816(acc[mi][ni], al[mi], &bh[ni >> 1][(ni & 1) * 2]);
        }
        if (++buf == NSTAGE) buf = 0;
    }

    const int gid = lane >> 2, tig = lane & 3;
#pragma unroll
    for (int mi = 0; mi < 2; ++mi) {
#pragma unroll
        for (int ni = 0; ni < 8; ++ni) {
            const int row = m0 + wm + mi * 16 + gid;
            const int col = n0 + wn + ni * 8 + 2 * tig;
            *(float2*)&C[(size_t)row * N + col] =
                make_float2(acc[mi][ni][0], acc[mi][ni][1]);
            *(float2*)&C[(size_t)(row + 8) * N + col] =
                make_float2(acc[mi][ni][2], acc[mi][ni][3]);
        }
    }
}

// fused QKV projection
__global__ __launch_bounds__(256, 1)
void qkv_gemm(const __nv_bfloat16* __restrict__ hsh, const __nv_bfloat16* __restrict__ hsl,
              const __nv_bfloat16* __restrict__ wqh, const __nv_bfloat16* __restrict__ wql,
              const __nv_bfloat16* __restrict__ wkh, const __nv_bfloat16* __restrict__ wkl,
              const __nv_bfloat16* __restrict__ wvh, const __nv_bfloat16* __restrict__ wvl,
              float* __restrict__ q, float* __restrict__ kt, float* __restrict__ vt) {
    extern __shared__ char smc[];
    const uint32_t smb = smem_u32(smc);
    const int nb = blockIdx.x;
    const __nv_bfloat16 *Bh, *Bl;
    float* C;
    int N, n0;
    if (nb < 32)      { Bh = wqh; Bl = wql; C = q;  N = NH  * HD; n0 = nb * 128; }
    else if (nb < 40) { Bh = wkh; Bl = wkl; C = kt; N = NKV * HD; n0 = (nb - 32) * 128; }
    else              { Bh = wvh; Bl = wvl; C = vt; N = NKV * HD; n0 = (nb - 40) * 128; }
    gemm_core(smb, hsh, hsl, Bh, Bl, C, blockIdx.y * BM, n0, N, HID);
}

// ================= 2-term fp16 GEMM (O-projection) =================
// C = A * B^T with A split (ah+al fp16), B rounded to fp16 once.
// Error = a*(b - bh) ~ 2^-11, direct path (no softmax amplification).
#define OST_BYTES (48 * 1024)
#define OOFF_AH   0
#define OOFF_AL   (16 * 1024)
#define OOFF_BH   (32 * 1024)
#define OGEMM_SMEM (NSTAGE * OST_BYTES)

__device__ __forceinline__ void load_stage_o(
    uint32_t sb, int tid,
    const __half* __restrict__ Ahi, const __half* __restrict__ Alo,
    const __half* __restrict__ Bh,
    int m0, int n0, int K, int k0) {
#pragma unroll
    for (int i = 0; i < 4; ++i) {
        int idx = tid + i * 256;
        int r = idx >> 3, c = idx & 7;
        uint32_t off = SWZ128((uint32_t)(r * 128 + c * 16));
        const size_t ga = (size_t)(m0 + r) * K + k0 + c * 8;
        cp16(sb + OOFF_AH + off, Ahi + ga);
        cp16(sb + OOFF_AL + off, Alo + ga);
        const size_t gb = (size_t)(n0 + r) * K + k0 + c * 8;
        cp16(sb + OOFF_BH + off, Bh + gb);
    }
    asm volatile("cp.async.commit_group;" ::: "memory");
}

__global__ __launch_bounds__(256, 1)
void hgemm_o(const __half* __restrict__ Ahi, const __half* __restrict__ Alo,
             const __half* __restrict__ Bh,
             float* __restrict__ C, int N, int K) {
    extern __shared__ char smc[];
    const uint32_t smb = smem_u32(smc);
    const int tid  = threadIdx.x;
    const int wid  = tid >> 5;
    const int lane = tid & 31;
    const int m0 = blockIdx.y * BM;
    const int n0 = blockIdx.x * BN;
    const int wm = (wid & 3) << 5;
    const int wn = (wid >> 2) << 6;

    const int a_row0 = wm + (lane & 15);
    const int a_csel = lane >> 4;
    const int b_row0 = wn + (lane & 7) + ((lane >> 4) << 3);
    const int b_csel = (lane >> 3) & 1;

    float acc[2][8][4];
#pragma unroll
    for (int mi = 0; mi < 2; ++mi)
#pragma unroll
        for (int ni = 0; ni < 8; ++ni)
#pragma unroll
            for (int r = 0; r < 4; ++r) acc[mi][ni][r] = 0.f;

    const int NIT = K / BK;
    load_stage_o(smb + 0 * OST_BYTES, tid, Ahi, Alo, Bh, m0, n0, K, 0);
    if (NIT > 1)
        load_stage_o(smb + 1 * OST_BYTES, tid, Ahi, Alo, Bh, m0, n0, K, BK);

    int buf = 0;
    for (int it = 0; it < NIT; ++it) {
        if (it + 1 < NIT) asm volatile("cp.async.wait_group 1;" ::: "memory");
        else              asm volatile("cp.async.wait_group 0;" ::: "memory");
        __syncthreads();

        if (it + 2 < NIT) {
            int nb = buf + 2; if (nb >= NSTAGE) nb -= NSTAGE;
            load_stage_o(smb + nb * OST_BYTES, tid, Ahi, Alo, Bh, m0, n0, K, (it + 2) * BK);
        }

        const uint32_t sb = smb + buf * OST_BYTES;
#pragma unroll
        for (int ks = 0; ks < 4; ++ks) {
            const int kc = ks * 2;
            uint32_t ah[2][4], al[2][4], bh[4][4];
#pragma unroll
            for (int mi = 0; mi < 2; ++mi) {
                uint32_t off = SWZ128((uint32_t)((a_row0 + mi * 16) * 128 + (kc + a_csel) * 16));
                ldsm4(ah[mi], sb + OOFF_AH + off);
                ldsm4(al[mi], sb + OOFF_AL + off);
            }
#pragma unroll
            for (int ni2 = 0; ni2 < 4; ++ni2) {
                uint32_t off = SWZ128((uint32_t)((b_row0 + ni2 * 16) * 128 + (kc + b_csel) * 16));
                ldsm4(bh[ni2], sb + OOFF_BH + off);
            }
#pragma unroll
            for (int ni = 0; ni < 8; ++ni)
#pragma unroll
                for (int mi = 0; mi < 2; ++mi)
                    mma16816h(acc[mi][ni], ah[mi], &bh[ni >> 1][(ni & 1) * 2]);
#pragma unroll
            for (int ni = 0; ni < 8; ++ni)
#pragma unroll
                for (int mi = 0; mi < 2; ++mi)
                    mma16816h(acc[mi][ni], al[mi], &bh[ni >> 1][(ni & 1) * 2]);
        }
        if (++buf == NSTAGE) buf = 0;
    }

    const int gid = lane >> 2, tig = lane & 3;
#pragma unroll
    for (int mi = 0; mi < 2; ++mi) {
#pragma unroll
        for (int ni = 0; ni < 8; ++ni) {
            const int row = m0 + wm + mi * 16 + gid;
            const int col = n0 + wn + ni * 8 + 2 * tig;
            *(float2*)&C[(size_t)row * N + col] =
                make_float2(acc[mi][ni][0], acc[mi][ni][1]);
            *(float2*)&C[(size_t)(row + 8) * N + col] =
                make_float2(acc[mi][ni][2], acc[mi][ni][3]);
        }
    }
}

// ---------------- flash attention (fp32, causal, GQA) ----------------
#define QPITCH 132
#define KPITCH 132
#define VPITCH 68
#define PPITCH 68
__global__ void attn_kernel(const float* __restrict__ Q, const float* __restrict__ K,
                            const float* __restrict__ V, float* __restrict__ O,
                            int S, float scale) {
    extern __shared__ float smf[];
    float* Qs = smf;
    float* Ks = Qs + 128 * QPITCH;
    float* Vt = Ks + 64 * KPITCH;
    float* Ps = Vt + 128 * VPITCH;

    int qt = blockIdx.x, h = blockIdx.y, b = blockIdx.z;
    int kvh = h / (NH / NKV);
    int tid = threadIdx.x;
    int tx = tid & 7, ty = tid >> 3;
    int q0 = qt * 128;

    for (int it = tid; it < 128 * 32; it += 256) {
        int r = it >> 5, dq = (it & 31) * 4;
        float4 v = *(const float4*)(Q + ((size_t)(b * S + q0 + r) * NH + h) * HD + dq);
        float* dst = &Qs[r * QPITCH + dq];
        dst[0] = v.x; dst[1] = v.y; dst[2] = v.z; dst[3] = v.w;
    }

    float m_i[4], l_i[4], Of[4][16];
#pragma unroll
    for (int i = 0; i < 4; ++i) {
        m_i[i] = -3.0e38f; l_i[i] = 0.f;
#pragma unroll
        for (int j = 0; j < 16; ++j) Of[i][j] = 0.f;
    }

    int ntiles = (q0 + 128) / 64;
    for (int t = 0; t < ntiles; ++t) {
        int kv0 = t * 64;
        __syncthreads();
        for (int it = tid; it < 64 * 32; it += 256) {
            int c = it >> 5, dq = (it & 31) * 4;
            const float* kp = K + ((size_t)(b * S + kv0 + c) * NKV + kvh) * HD + dq;
            float4 kk = *(const float4*)kp;
            float* kd = &Ks[c * KPITCH + dq];
            kd[0] = kk.x; kd[1] = kk.y; kd[2] = kk.z; kd[3] = kk.w;
            const float* vp = V + ((size_t)(b * S + kv0 + c) * NKV + kvh) * HD + dq;
            float4 vv = *(const float4*)vp;
            Vt[(dq + 0) * VPITCH + c] = vv.x;
            Vt[(dq + 1) * VPITCH + c] = vv.y;
            Vt[(dq + 2) * VPITCH + c] = vv.z;
            Vt[(dq + 3) * VPITCH + c] = vv.w;
        }
        __syncthreads();

        float acc[4][8];
#pragma unroll
        for (int i = 0; i < 4; ++i)
#pragma unroll
            for (int j = 0; j < 8; ++j) acc[i][j] = 0.f;
#pragma unroll 4
        for (int k4 = 0; k4 < 32; ++k4) {
            float4 qa[4];
#pragma unroll
            for (int i = 0; i < 4; ++i)
                qa[i] = *(const float4*)&Qs[(ty * 4 + i) * QPITCH + k4 * 4];
#pragma unroll
            for (int j = 0; j < 8; ++j) {
                float4 kb = *(const float4*)&Ks[(tx + 8 * j) * KPITCH + k4 * 4];
#pragma unroll
                for (int i = 0; i < 4; ++i)
                    acc[i][j] += qa[i].x * kb.x + qa[i].y * kb.y
                               + qa[i].z * kb.z + qa[i].w * kb.w;
            }
        }

#pragma unroll
        for (int i = 0; i < 4; ++i) {
            int qi = q0 + ty * 4 + i;
            float mrow = -3.0e38f;
#pragma unroll
            for (int j = 0; j < 8; ++j) {
                int kidx = kv0 + tx + 8 * j;
                float sv = (kidx <= qi) ? acc[i][j] * scale : -1.0e30f;
                acc[i][j] = sv;
                mrow = fmaxf(mrow, sv);
            }
            mrow = fmaxf(mrow, __shfl_xor_sync(0xffffffffu, mrow, 1));
            mrow = fmaxf(mrow, __shfl_xor_sync(0xffffffffu, mrow, 2));
            mrow = fmaxf(mrow, __shfl_xor_sync(0xffffffffu, mrow, 4));
            float mnew  = fmaxf(m_i[i], mrow);
            float alpha = expf(m_i[i] - mnew);
            float lsum = 0.f;
#pragma unroll
            for (int j = 0; j < 8; ++j) {
                float p = expf(acc[i][j] - mnew);
                acc[i][j] = p;
                lsum += p;
            }
            lsum += __shfl_xor_sync(0xffffffffu, lsum, 1);
            lsum += __shfl_xor_sync(0xffffffffu, lsum, 2);
            lsum += __shfl_xor_sync(0xffffffffu, lsum, 4);
            l_i[i] = l_i[i] * alpha + lsum;
            m_i[i] = mnew;
#pragma unroll
            for (int j = 0; j < 16; ++j) Of[i][j] *= alpha;
#pragma unroll
            for (int j = 0; j < 8; ++j)
                Ps[(ty * 4 + i) * PPITCH + tx + 8 * j] = acc[i][j];
        }
        __syncthreads();

#pragma unroll 4
        for (int k4 = 0; k4 < 16; ++k4) {
            float4 pa[4];
#pragma unroll
            for (int i = 0; i < 4; ++i)
                pa[i] = *(const float4*)&Ps[(ty * 4 + i) * PPITCH + k4 * 4];
#pragma unroll
            for (int j = 0; j < 16; ++j) {
                float4 vb = *(const float4*)&Vt[(tx + 8 * j) * VPITCH + k4 * 4];
#pragma unroll
                for (int i = 0; i < 4; ++i)
                    Of[i][j] += pa[i].x * vb.x + pa[i].y * vb.y
                              + pa[i].z * vb.z + pa[i].w * vb.w;
            }
        }
    }

#pragma unroll
    for (int i = 0; i < 4; ++i) {
        int row = q0 + ty * 4 + i;
        float inv = 1.f / l_i[i];
        float* op = O + ((size_t)(b * S + row) * NH + h) * HD;
#pragma unroll
        for (int j = 0; j < 16; ++j)
            op[tx + 8 * j] = Of[i][j] * inv;
    }
}

// ---------------- launch ----------------
extern "C" void kernel_launch(void* const* d_in, const int* in_sizes, int n_in,
                              void* d_out, int out_size) {
    const float* hs  = (const float*)d_in[0];
    const float* wq  = (const float*)d_in[1];
    const float* wk  = (const float*)d_in[2];
    const float* wv  = (const float*)d_in[3];
    const float* wo  = (const float*)d_in[4];
    const int*   pos = (const int*)  d_in[6];

    int nnz = in_sizes[0] / HID;
    int b   = in_sizes[10] - 1;
    int s   = nnz / b;

    float *q, *kt, *vt, *kg, *vg, *attn;
    cudaGetSymbolAddress((void**)&q,    g_q);
    cudaGetSymbolAddress((void**)&kt,   g_kt);
    cudaGetSymbolAddress((void**)&vt,   g_vt);
    cudaGetSymbolAddress((void**)&kg,   g_kg);
    cudaGetSymbolAddress((void**)&vg,   g_vg);
    cudaGetSymbolAddress((void**)&attn, g_attn);

    __nv_bfloat16 *hsh, *hsl, *wqh, *wql, *wkh, *wkl, *wvh, *wvl;
    __half *woh, *ath, *atl;
    cudaGetSymbolAddress((void**)&hsh, g_hs_hi);
    cudaGetSymbolAddress((void**)&hsl, g_hs_lo);
    cudaGetSymbolAddress((void**)&wqh, g_wq_hi);
    cudaGetSymbolAddress((void**)&wql, g_wq_lo);
    cudaGetSymbolAddress((void**)&wkh, g_wk_hi);
    cudaGetSymbolAddress((void**)&wkl, g_wk_lo);
    cudaGetSymbolAddress((void**)&wvh, g_wv_hi);
    cudaGetSymbolAddress((void**)&wvl, g_wv_lo);
    cudaGetSymbolAddress((void**)&woh, g_wo_h);
    cudaGetSymbolAddress((void**)&ath, g_at_hi);
    cudaGetSymbolAddress((void**)&atl, g_at_lo);

    const size_t ATTN_SMEM =
        (size_t)(128 * QPITCH + 64 * KPITCH + 128 * VPITCH + 128 * PPITCH) * sizeof(float);
    cudaFuncSetAttribute(attn_kernel, cudaFuncAttributeMaxDynamicSharedMemorySize,
                         (int)ATTN_SMEM);
    cudaFuncSetAttribute(qkv_gemm, cudaFuncAttributeMaxDynamicSharedMemorySize, GEMM_SMEM);
    cudaFuncSetAttribute(hgemm_o,  cudaFuncAttributeMaxDynamicSharedMemorySize, OGEMM_SMEM);

    // 1. RoPE cos/sin table
    rope_table_kernel<<<s, 64>>>();

    // 2. split-convert activations + weights
    {
        int n4;
        n4 = nnz * HID / 4;      cvt_split_kernel<<<(n4 + 255) / 256, 256>>>(hs, hsh, hsl, n4);
        n4 = NH  * HD * HID / 4; cvt_split_kernel<<<(n4 + 255) / 256, 256>>>(wq, wqh, wql, n4);
        n4 = NKV * HD * HID / 4; cvt_split_kernel<<<(n4 + 255) / 256, 256>>>(wk, wkh, wkl, n4);
        n4 = NKV * HD * HID / 4; cvt_split_kernel<<<(n4 + 255) / 256, 256>>>(wv, wvh, wvl, n4);
        n4 = HID * NH * HD / 4;  cvt_f16_kernel<<<(n4 + 255) / 256, 256>>>(wo, woh, n4);
    }

    // 3. fused Q/K/V projection (3xBF16)
    qkv_gemm<<<dim3(48, nnz / BM), 256, GEMM_SMEM>>>(hsh, hsl, wqh, wql, wkh, wkl,
                                                     wvh, wvl, q, kt, vt);

    // 4. RoPE + paged-KV scatter
    rope_q_kernel<<<nnz, 256>>>(q, pos);
    ropekv_scatter_kernel<<<nnz, 256>>>(pos, s);

    // 5. causal GQA flash attention (fp32)
    float scale = 1.0f / sqrtf((float)HD);
    attn_kernel<<<dim3(s / 128, NH, b), 256, ATTN_SMEM>>>(q, kg, vg, attn, s, scale);

    // 6. output projection (2-term fp16: A split, B rounded)
    {
        int n4 = nnz * NH * HD / 4;
        cvt_split_f16_kernel<<<(n4 + 255) / 256, 256>>>(attn, ath, atl, n4);
    }
    hgemm_o<<<dim3(HID / BN, nnz / BM), 256, OGEMM_SMEM>>>(ath, atl, woh,
                                                           (float*)d_out, HID, NH * HD);
}

// round 14
// speedup vs baseline: 1.3382x; 1.1177x over previous
#include <cuda_runtime.h>
#include <cuda_bf16.h>
#include <cuda_fp16.h>
#include <math.h>
#include <stdint.h>

// ---------------- problem constants ----------------
#define HID 4096
#define NH  32
#define NKV 8
#define HD  128
#define MAX_NNZ 4096
#define MAX_S   1024

// ---------------- device scratch (no allocs allowed) ----------------
__device__ float g_q   [(size_t)MAX_NNZ * NH  * HD];
__device__ float g_kt  [(size_t)MAX_NNZ * NKV * HD];
__device__ float g_vt  [(size_t)MAX_NNZ * NKV * HD];
__device__ float g_kg  [(size_t)MAX_NNZ * NKV * HD];
__device__ float g_vg  [(size_t)MAX_NNZ * NKV * HD];
__device__ float g_attn[(size_t)MAX_NNZ * NH  * HD];
__device__ float g_cos [MAX_S * 64];
__device__ float g_sin [MAX_S * 64];

// bf16 split operands (Q/K projections — softmax-amplified path)
__device__ __nv_bfloat16 g_hs_hi[(size_t)MAX_NNZ * HID];
__device__ __nv_bfloat16 g_hs_lo[(size_t)MAX_NNZ * HID];
__device__ __nv_bfloat16 g_wq_hi[(size_t)NH  * HD * HID];
__device__ __nv_bfloat16 g_wq_lo[(size_t)NH  * HD * HID];
__device__ __nv_bfloat16 g_wk_hi[(size_t)NKV * HD * HID];
__device__ __nv_bfloat16 g_wk_lo[(size_t)NKV * HD * HID];
// fp16 operands (V / O projections — direct path)
__device__ __half g_hs_h16[(size_t)MAX_NNZ * HID];
__device__ __half g_hs_l16[(size_t)MAX_NNZ * HID];
__device__ __half g_wv_h  [(size_t)NKV * HD * HID];
__device__ __half g_wo_h  [(size_t)HID * NH * HD];
__device__ __half g_at_h  [(size_t)MAX_NNZ * NH * HD];

// ---------------- helpers ----------------
__device__ __forceinline__ uint32_t smem_u32(const void* p) {
    uint32_t a;
    asm("{ .reg .u64 t; cvta.to.shared.u64 t, %1; cvt.u32.u64 %0, t; }" : "=r"(a) : "l"(p));
    return a;
}
#define SWZ128(o) ((o) ^ (((o) >> 3) & 0x70))

__device__ __forceinline__ void mma16816(float* c, const uint32_t* a, const uint32_t* b) {
    asm volatile(
        "mma.sync.aligned.m16n8k16.row.col.f32.bf16.bf16.f32 "
        "{%0,%1,%2,%3}, {%4,%5,%6,%7}, {%8,%9}, {%0,%1,%2,%3};\n"
        : "+f"(c[0]), "+f"(c[1]), "+f"(c[2]), "+f"(c[3])
        : "r"(a[0]), "r"(a[1]), "r"(a[2]), "r"(a[3]), "r"(b[0]), "r"(b[1]));
}
__device__ __forceinline__ void mma16816h(float* c, const uint32_t* a, const uint32_t* b) {
    asm volatile(
        "mma.sync.aligned.m16n8k16.row.col.f32.f16.f16.f32 "
        "{%0,%1,%2,%3}, {%4,%5,%6,%7}, {%8,%9}, {%0,%1,%2,%3};\n"
        : "+f"(c[0]), "+f"(c[1]), "+f"(c[2]), "+f"(c[3])
        : "r"(a[0]), "r"(a[1]), "r"(a[2]), "r"(a[3]), "r"(b[0]), "r"(b[1]));
}
__device__ __forceinline__ void ldsm4(uint32_t* r, uint32_t addr) {
    asm volatile("ldmatrix.sync.aligned.m8n8.x4.shared.b16 {%0,%1,%2,%3}, [%4];"
        : "=r"(r[0]), "=r"(r[1]), "=r"(r[2]), "=r"(r[3]) : "r"(addr));
}
__device__ __forceinline__ void cp16(uint32_t dst, const void* src) {
    asm volatile("cp.async.cg.shared.global [%0], [%1], 16;" :: "r"(dst), "l"(src));
}

// ---------------- converts ----------------
__global__ void cvt_split_kernel(const float* __restrict__ x,
                                 __nv_bfloat16* __restrict__ hi,
                                 __nv_bfloat16* __restrict__ lo, int n4) {
    int i = blockIdx.x * blockDim.x + threadIdx.x;
    if (i >= n4) return;
    float4 v = ((const float4*)x)[i];
    union { __nv_bfloat16 b[4]; uint2 u; } H, L;
    H.b[0] = __float2bfloat16_rn(v.x);
    H.b[1] = __float2bfloat16_rn(v.y);
    H.b[2] = __float2bfloat16_rn(v.z);
    H.b[3] = __float2bfloat16_rn(v.w);
    L.b[0] = __float2bfloat16_rn(v.x - __bfloat162float(H.b[0]));
    L.b[1] = __float2bfloat16_rn(v.y - __bfloat162float(H.b[1]));
    L.b[2] = __float2bfloat16_rn(v.z - __bfloat162float(H.b[2]));
    L.b[3] = __float2bfloat16_rn(v.w - __bfloat162float(H.b[3]));
    ((uint2*)hi)[i] = H.u;
    ((uint2*)lo)[i] = L.u;
}

__global__ void cvt_split_f16_kernel(const float* __restrict__ x,
                                     __half* __restrict__ hi,
                                     __half* __restrict__ lo, int n4) {
    int i = blockIdx.x * blockDim.x + threadIdx.x;
    if (i >= n4) return;
    float4 v = ((const float4*)x)[i];
    union { __half h[4]; uint2 u; } H, L;
    H.h[0] = __float2half_rn(v.x);
    H.h[1] = __float2half_rn(v.y);
    H.h[2] = __float2half_rn(v.z);
    H.h[3] = __float2half_rn(v.w);
    L.h[0] = __float2half_rn(v.x - __half2float(H.h[0]));
    L.h[1] = __float2half_rn(v.y - __half2float(H.h[1]));
    L.h[2] = __float2half_rn(v.z - __half2float(H.h[2]));
    L.h[3] = __float2half_rn(v.w - __half2float(H.h[3]));
    ((uint2*)hi)[i] = H.u;
    ((uint2*)lo)[i] = L.u;
}

__global__ void cvt_f16_kernel(const float* __restrict__ x,
                               __half* __restrict__ h, int n4) {
    int i = blockIdx.x * blockDim.x + threadIdx.x;
    if (i >= n4) return;
    float4 v = ((const float4*)x)[i];
    union { __half h[4]; uint2 u; } H;
    H.h[0] = __float2half_rn(v.x);
    H.h[1] = __float2half_rn(v.y);
    H.h[2] = __float2half_rn(v.z);
    H.h[3] = __float2half_rn(v.w);
    ((uint2*)h)[i] = H.u;
}

// ---------------- RoPE table ----------------
__global__ void rope_table_kernel() {
    int p = blockIdx.x;
    int j = threadIdx.x;
    double e    = (double)j / 64.0;
    double freq = exp(-e * log(500000.0));
    const double PI = 3.14159265358979323846;
    double wavelen = 2.0 * PI / freq;
    double f;
    if (wavelen < 2048.0)       f = freq;
    else if (wavelen > 8192.0)  f = freq / 8.0;
    else {
        double smooth = (8192.0 / wavelen - 1.0) / 3.0;
        f = (1.0 - smooth) * freq / 8.0 + smooth * freq;
    }
    double ang = (double)p * f;
    g_cos[p * 64 + j] = (float)cos(ang);
    g_sin[p * 64 + j] = (float)sin(ang);
}

__global__ void rope_q_kernel(float* __restrict__ q, const int* __restrict__ pos) {
    int i = blockIdx.x;
    int p = pos[i];
    const float* cr = g_cos + (size_t)p * 64;
    const float* sr = g_sin + (size_t)p * 64;
    float* base = q + (size_t)i * (NH * HD);
    for (int idx = threadIdx.x; idx < NH * 64; idx += blockDim.x) {
        int h = idx >> 6, j = idx & 63;
        float c = cr[j], s = sr[j];
        float* hb = base + h * HD;
        float x1 = hb[j], x2 = hb[j + 64];
        hb[j]      = x1 * c - x2 * s;
        hb[j + 64] = x2 * c + x1 * s;
    }
}

__global__ void ropekv_scatter_kernel(const int* __restrict__ pos, int s_per_b) {
    int i = blockIdx.x;
    int b = i / s_per_b;
    int p = pos[i];
    int dst = b * s_per_b + p;
    const float* cr = g_cos + (size_t)p * 64;
    const float* sr = g_sin + (size_t)p * 64;
    const float* kin  = g_kt + (size_t)i   * (NKV * HD);
    float*       kout = g_kg + (size_t)dst * (NKV * HD);
    for (int idx = threadIdx.x; idx < NKV * 64; idx += blockDim.x) {
        int h = idx >> 6, j = idx & 63;
        float c = cr[j], s = sr[j];
        float x1 = kin[h * HD + j], x2 = kin[h * HD + j + 64];
        kout[h * HD + j]      = x1 * c - x2 * s;
        kout[h * HD + j + 64] = x2 * c + x1 * s;
    }
    const float* vin  = g_vt + (size_t)i   * (NKV * HD);
    float*       vout = g_vg + (size_t)dst * (NKV * HD);
    for (int idx = threadIdx.x; idx < NKV * HD; idx += blockDim.x)
        vout[idx] = vin[idx];
}

// ================= GEMM cores =================
#define BM 128
#define BN 128
#define BK 64
#define NSTAGE   3
// 3xbf16 core stage layout (64KB)
#define ST_BYTES (64 * 1024)
#define OFF_AH   0
#define OFF_AL   (16 * 1024)
#define OFF_BH   (32 * 1024)
#define OFF_BL   (48 * 1024)
#define GEMM_SMEM (NSTAGE * ST_BYTES)

// ---- 3xBF16 core (Q/K projections) ----
__device__ __forceinline__ void load_stage(
    uint32_t sb, int tid,
    const __nv_bfloat16* __restrict__ Ahi, const __nv_bfloat16* __restrict__ Alo,
    const __nv_bfloat16* __restrict__ Bhi, const __nv_bfloat16* __restrict__ Blo,
    int m0, int n0, int K, int k0) {
#pragma unroll
    for (int i = 0; i < 4; ++i) {
        int idx = tid + i * 256;
        int r = idx >> 3, c = idx & 7;
        uint32_t off = SWZ128((uint32_t)(r * 128 + c * 16));
        const size_t ga = (size_t)(m0 + r) * K + k0 + c * 8;
        cp16(sb + OFF_AH + off, Ahi + ga);
        cp16(sb + OFF_AL + off, Alo + ga);
        const size_t gb = (size_t)(n0 + r) * K + k0 + c * 8;
        cp16(sb + OFF_BH + off, Bhi + gb);
        cp16(sb + OFF_BL + off, Blo + gb);
    }
    asm volatile("cp.async.commit_group;" ::: "memory");
}

__device__ __forceinline__ void gemm_core(
    uint32_t smb,
    const __nv_bfloat16* __restrict__ Ahi, const __nv_bfloat16* __restrict__ Alo,
    const __nv_bfloat16* __restrict__ Bhi, const __nv_bfloat16* __restrict__ Blo,
    float* __restrict__ C, int m0, int n0, int N, int K) {
    const int tid  = threadIdx.x;
    const int wid  = tid >> 5;
    const int lane = tid & 31;
    const int wm = (wid & 3) << 5;
    const int wn = (wid >> 2) << 6;

    const int a_row0 = wm + (lane & 15);
    const int a_csel = lane >> 4;
    const int b_row0 = wn + (lane & 7) + ((lane >> 4) << 3);
    const int b_csel = (lane >> 3) & 1;

    float acc[2][8][4];
#pragma unroll
    for (int mi = 0; mi < 2; ++mi)
#pragma unroll
        for (int ni = 0; ni < 8; ++ni)
#pragma unroll
            for (int r = 0; r < 4; ++r) acc[mi][ni][r] = 0.f;

    const int NIT = K / BK;
    load_stage(smb + 0 * ST_BYTES, tid, Ahi, Alo, Bhi, Blo, m0, n0, K, 0);
    if (NIT > 1)
        load_stage(smb + 1 * ST_BYTES, tid, Ahi, Alo, Bhi, Blo, m0, n0, K, BK);

    int buf = 0;
    for (int it = 0; it < NIT; ++it) {
        if (it + 1 < NIT) asm volatile("cp.async.wait_group 1;" ::: "memory");
        else              asm volatile("cp.async.wait_group 0;" ::: "memory");
        __syncthreads();

        if (it + 2 < NIT) {
            int nb = buf + 2; if (nb >= NSTAGE) nb -= NSTAGE;
            load_stage(smb + nb * ST_BYTES, tid, Ahi, Alo, Bhi, Blo, m0, n0, K, (it + 2) * BK);
        }

        const uint32_t sb = smb + buf * ST_BYTES;
#pragma unroll
        for (int ks = 0; ks < 4; ++ks) {
            const int kc = ks * 2;
            uint32_t ah[2][4], al[2][4], bh[4][4], bl[4][4];
#pragma unroll
            for (int mi = 0; mi < 2; ++mi) {
                uint32_t off = SWZ128((uint32_t)((a_row0 + mi * 16) * 128 + (kc + a_csel) * 16));
                ldsm4(ah[mi], sb + OFF_AH + off);
                ldsm4(al[mi], sb + OFF_AL + off);
            }
#pragma unroll
            for (int ni2 = 0; ni2 < 4; ++ni2) {
                uint32_t off = SWZ128((uint32_t)((b_row0 + ni2 * 16) * 128 + (kc + b_csel) * 16));
                ldsm4(bh[ni2], sb + OFF_BH + off);
                ldsm4(bl[ni2], sb + OFF_BL + off);
            }
#pragma unroll
            for (int ni = 0; ni < 8; ++ni)
#pragma unroll
                for (int mi = 0; mi < 2; ++mi)
                    mma16816(acc[mi][ni], ah[mi], &bh[ni >> 1][(ni & 1) * 2]);
#pragma unroll
            for (int ni = 0; ni < 8; ++ni)
#pragma unroll
                for (int mi = 0; mi < 2; ++mi)
                    mma16816(acc[mi][ni], ah[mi], &bl[ni >> 1][(ni & 1) * 2]);
#pragma unroll
            for (int ni = 0; ni < 8; ++ni)
#pragma unroll
                for (int mi = 0; mi < 2; ++mi)
                    mma16816(acc[mi][ni], al[mi], &bh[ni >> 1][(ni & 1) * 2]);
        }
        if (++buf == NSTAGE) buf = 0;
    }

    const int gid = lane >> 2, tig = lane & 3;
#pragma unroll
    for (int mi = 0; mi < 2; ++mi) {
#pragma unroll
        for (int ni = 0; ni < 8; ++ni) {
            const int row = m0 + wm + mi * 16 + gid;
            const int col = n0 + wn + ni * 8 + 2 * tig;
            *(float2*)&C[(size_t)row * N + col] =
                make_float2(acc[mi][ni][0], acc[mi][ni][1]);
            *(float2*)&C[(size_t)(row + 8) * N + col] =
                make_float2(acc[mi][ni][2], acc[mi][ni][3]);
        }
    }
}

// ---- fp16 core, NT terms (A exact in NT pieces, B rounded) ----
// stage layout: Ah @0 (16K), Al @16K (NT==2), Bh @OFFB
template <int NT>
__device__ __forceinline__ void gemm_core_f16(
    uint32_t smb,
    const __half* __restrict__ Ahi, const __half* __restrict__ Alo,
    const __half* __restrict__ Bh,
    float* __restrict__ C, int m0, int n0, int N, int K) {
    constexpr uint32_t STB  = (NT == 2) ? 48 * 1024 : 32 * 1024;
    constexpr uint32_t OFFB = (NT == 2) ? 32 * 1024 : 16 * 1024;
    const int tid  = threadIdx.x;
    const int wid  = tid >> 5;
    const int lane = tid & 31;
    const int wm = (wid & 3) << 5;
    const int wn = (wid >> 2) << 6;

    const int a_row0 = wm + (lane & 15);
    const int a_csel = lane >> 4;
    const int b_row0 = wn + (lane & 7) + ((lane >> 4) << 3);
    const int b_csel = (lane >> 3) & 1;

    auto load_f16 = [&](uint32_t sb, int k0) {
#pragma unroll
        for (int i = 0; i < 4; ++i) {
            int idx = tid + i * 256;
            int r = idx >> 3, c = idx & 7;
            uint32_t off = SWZ128((uint32_t)(r * 128 + c * 16));
            const size_t ga = (size_t)(m0 + r) * K + k0 + c * 8;
            cp16(sb + off, Ahi + ga);
            if (NT == 2) cp16(sb + 16 * 1024 + off, Alo + ga);
            const size_t gb = (size_t)(n0 + r) * K + k0 + c * 8;
            cp16(sb + OFFB + off, Bh + gb);
        }
        asm volatile("cp.async.commit_group;" ::: "memory");
    };

    float acc[2][8][4];
#pragma unroll
    for (int mi = 0; mi < 2; ++mi)
#pragma unroll
        for (int ni = 0; ni < 8; ++ni)
#pragma unroll
            for (int r = 0; r < 4; ++r) acc[mi][ni][r] = 0.f;

    const int NIT = K / BK;
    load_f16(smb + 0 * STB, 0);
    if (NIT > 1) load_f16(smb + 1 * STB, BK);

    int buf = 0;
    for (int it = 0; it < NIT; ++it) {
        if (it + 1 < NIT) asm volatile("cp.async.wait_group 1;" ::: "memory");
        else              asm volatile("cp.async.wait_group 0;" ::: "memory");
        __syncthreads();

        if (it + 2 < NIT) {
            int nb = buf + 2; if (nb >= NSTAGE) nb -= NSTAGE;
            load_f16(smb + nb * STB, (it + 2) * BK);
        }

        const uint32_t sb = smb + buf * STB;
#pragma unroll
        for (int ks = 0; ks < 4; ++ks) {
            const int kc = ks * 2;
            uint32_t ah[2][4], al[2][4], bh[4][4];
#pragma unroll
            for (int mi = 0; mi < 2; ++mi) {
                uint32_t off = SWZ128((uint32_t)((a_row0 + mi * 16) * 128 + (kc + a_csel) * 16));
                ldsm4(ah[mi], sb + off);
                if (NT == 2) ldsm4(al[mi], sb + 16 * 1024 + off);
            }
#pragma unroll
            for (int ni2 = 0; ni2 < 4; ++ni2) {
                uint32_t off = SWZ128((uint32_t)((b_row0 + ni2 * 16) * 128 + (kc + b_csel) * 16));
                ldsm4(bh[ni2], sb + OFFB + off);
            }
#pragma unroll
            for (int ni = 0; ni < 8; ++ni)
#pragma unroll
                for (int mi = 0; mi < 2; ++mi)
                    mma16816h(acc[mi][ni], ah[mi], &bh[ni >> 1][(ni & 1) * 2]);
            if (NT == 2) {
#pragma unroll
                for (int ni = 0; ni < 8; ++ni)
#pragma unroll
                    for (int mi = 0; mi < 2; ++mi)
                        mma16816h(acc[mi][ni], al[mi], &bh[ni >> 1][(ni & 1) * 2]);
            }
        }
        if (++buf == NSTAGE) buf = 0;
    }

    const int gid = lane >> 2, tig = lane & 3;
#pragma unroll
    for (int mi = 0; mi < 2; ++mi) {
#pragma unroll
        for (int ni = 0; ni < 8; ++ni) {
            const int row = m0 + wm + mi * 16 + gid;
            const int col = n0 + wn + ni * 8 + 2 * tig;
            *(float2*)&C[(size_t)row * N + col] =
                make_float2(acc[mi][ni][0], acc[mi][ni][1]);
            *(float2*)&C[(size_t)(row + 8) * N + col] =
                make_float2(acc[mi][ni][2], acc[mi][ni][3]);
        }
    }
}

// fused QKV projection: 48 n-blocks (32 Q | 8 K bf16 path, 8 V fp16 path)
__global__ __launch_bounds__(256, 1)
void qkv_gemm(const __nv_bfloat16* __restrict__ hsh, const __nv_bfloat16* __restrict__ hsl,
              const __nv_bfloat16* __restrict__ wqh, const __nv_bfloat16* __restrict__ wql,
              const __nv_bfloat16* __restrict__ wkh, const __nv_bfloat16* __restrict__ wkl,
              const __half* __restrict__ hsh16, const __half* __restrict__ hsl16,
              const __half* __restrict__ wvh16,
              float* __restrict__ q, float* __restrict__ kt, float* __restrict__ vt) {
    extern __shared__ char smc[];
    const uint32_t smb = smem_u32(smc);
    const int nb = blockIdx.x;
    const int m0 = blockIdx.y * BM;
    if (nb < 32) {
        gemm_core(smb, hsh, hsl, wqh, wql, q, m0, nb * 128, NH * HD, HID);
    } else if (nb < 40) {
        gemm_core(smb, hsh, hsl, wkh, wkl, kt, m0, (nb - 32) * 128, NKV * HD, HID);
    } else {
        gemm_core_f16<2>(smb, hsh16, hsl16, wvh16, vt, m0, (nb - 40) * 128, NKV * HD, HID);
    }
}

// O-projection: 1-term fp16 (both operands rounded; direct path)
__global__ __launch_bounds__(256, 1)
void hgemm_o(const __half* __restrict__ Ah, const __half* __restrict__ Bh,
             float* __restrict__ C, int N, int K) {
    extern __shared__ char smc[];
    gemm_core_f16<1>(smem_u32(smc), Ah, (const __half*)nullptr, Bh, C,
                     blockIdx.y * BM, blockIdx.x * BN, N, K);
}

// ---------------- flash attention (fp32, causal, GQA) ----------------
#define QPITCH 132
#define KPITCH 132
#define VPITCH 68
#define PPITCH 68
__global__ void attn_kernel(const float* __restrict__ Q, const float* __restrict__ K,
                            const float* __restrict__ V, float* __restrict__ O,
                            int S, float scale) {
    extern __shared__ float smf[];
    float* Qs = smf;
    float* Ks = Qs + 128 * QPITCH;
    float* Vt = Ks + 64 * KPITCH;
    float* Ps = Vt + 128 * VPITCH;

    int qt = blockIdx.x, h = blockIdx.y, b = blockIdx.z;
    int kvh = h / (NH / NKV);
    int tid = threadIdx.x;
    int tx = tid & 7, ty = tid >> 3;
    int q0 = qt * 128;

    for (int it = tid; it < 128 * 32; it += 256) {
        int r = it >> 5, dq = (it & 31) * 4;
        float4 v = *(const float4*)(Q + ((size_t)(b * S + q0 + r) * NH + h) * HD + dq);
        float* dst = &Qs[r * QPITCH + dq];
        dst[0] = v.x; dst[1] = v.y; dst[2] = v.z; dst[3] = v.w;
    }

    float m_i[4], l_i[4], Of[4][16];
#pragma unroll
    for (int i = 0; i < 4; ++i) {
        m_i[i] = -3.0e38f; l_i[i] = 0.f;
#pragma unroll
        for (int j = 0; j < 16; ++j) Of[i][j] = 0.f;
    }

    int ntiles = (q0 + 128) / 64;
    for (int t = 0; t < ntiles; ++t) {
        int kv0 = t * 64;
        __syncthreads();
        for (int it = tid; it < 64 * 32; it += 256) {
            int c = it >> 5, dq = (it & 31) * 4;
            const float* kp = K + ((size_t)(b * S + kv0 + c) * NKV + kvh) * HD + dq;
            float4 kk = *(const float4*)kp;
            float* kd = &Ks[c * KPITCH + dq];
            kd[0] = kk.x; kd[1] = kk.y; kd[2] = kk.z; kd[3] = kk.w;
            const float* vp = V + ((size_t)(b * S + kv0 + c) * NKV + kvh) * HD + dq;
            float4 vv = *(const float4*)vp;
            Vt[(dq + 0) * VPITCH + c] = vv.x;
            Vt[(dq + 1) * VPITCH + c] = vv.y;
            Vt[(dq + 2) * VPITCH + c] = vv.z;
            Vt[(dq + 3) * VPITCH + c] = vv.w;
        }
        __syncthreads();

        float acc[4][8];
#pragma unroll
        for (int i = 0; i < 4; ++i)
#pragma unroll
            for (int j = 0; j < 8; ++j) acc[i][j] = 0.f;
#pragma unroll 4
        for (int k4 = 0; k4 < 32; ++k4) {
            float4 qa[4];
#pragma unroll
            for (int i = 0; i < 4; ++i)
                qa[i] = *(const float4*)&Qs[(ty * 4 + i) * QPITCH + k4 * 4];
#pragma unroll
            for (int j = 0; j < 8; ++j) {
                float4 kb = *(const float4*)&Ks[(tx + 8 * j) * KPITCH + k4 * 4];
#pragma unroll
                for (int i = 0; i < 4; ++i)
                    acc[i][j] += qa[i].x * kb.x + qa[i].y * kb.y
                               + qa[i].z * kb.z + qa[i].w * kb.w;
            }
        }

#pragma unroll
        for (int i = 0; i < 4; ++i) {
            int qi = q0 + ty * 4 + i;
            float mrow = -3.0e38f;
#pragma unroll
            for (int j = 0; j < 8; ++j) {
                int kidx = kv0 + tx + 8 * j;
                float sv = (kidx <= qi) ? acc[i][j] * scale : -1.0e30f;
                acc[i][j] = sv;
                mrow = fmaxf(mrow, sv);
            }
            mrow = fmaxf(mrow, __shfl_xor_sync(0xffffffffu, mrow, 1));
            mrow = fmaxf(mrow, __shfl_xor_sync(0xffffffffu, mrow, 2));
            mrow = fmaxf(mrow, __shfl_xor_sync(0xffffffffu, mrow, 4));
            float mnew  = fmaxf(m_i[i], mrow);
            float alpha = expf(m_i[i] - mnew);
            float lsum = 0.f;
#pragma unroll
            for (int j = 0; j < 8; ++j) {
                float p = expf(acc[i][j] - mnew);
                acc[i][j] = p;
                lsum += p;
            }
            lsum += __shfl_xor_sync(0xffffffffu, lsum, 1);
            lsum += __shfl_xor_sync(0xffffffffu, lsum, 2);
            lsum += __shfl_xor_sync(0xffffffffu, lsum, 4);
            l_i[i] = l_i[i] * alpha + lsum;
            m_i[i] = mnew;
#pragma unroll
            for (int j = 0; j < 16; ++j) Of[i][j] *= alpha;
#pragma unroll
            for (int j = 0; j < 8; ++j)
                Ps[(ty * 4 + i) * PPITCH + tx + 8 * j] = acc[i][j];
        }
        __syncthreads();

#pragma unroll 4
        for (int k4 = 0; k4 < 16; ++k4) {
            float4 pa[4];
#pragma unroll
            for (int i = 0; i < 4; ++i)
                pa[i] = *(const float4*)&Ps[(ty * 4 + i) * PPITCH + k4 * 4];
#pragma unroll
            for (int j = 0; j < 16; ++j) {
                float4 vb = *(const float4*)&Vt[(tx + 8 * j) * VPITCH + k4 * 4];
#pragma unroll
                for (int i = 0; i < 4; ++i)
                    Of[i][j] += pa[i].x * vb.x + pa[i].y * vb.y
                              + pa[i].z * vb.z + pa[i].w * vb.w;
            }
        }
    }

#pragma unroll
    for (int i = 0; i < 4; ++i) {
        int row = q0 + ty * 4 + i;
        float inv = 1.f / l_i[i];
        float* op = O + ((size_t)(b * S + row) * NH + h) * HD;
#pragma unroll
        for (int j = 0; j < 16; ++j)
            op[tx + 8 * j] = Of[i][j] * inv;
    }
}

// ---------------- launch ----------------
extern "C" void kernel_launch(void* const* d_in, const int* in_sizes, int n_in,
                              void* d_out, int out_size) {
    const float* hs  = (const float*)d_in[0];
    const float* wq  = (const float*)d_in[1];
    const float* wk  = (const float*)d_in[2];
    const float* wv  = (const float*)d_in[3];
    const float* wo  = (const float*)d_in[4];
    const int*   pos = (const int*)  d_in[6];

    int nnz = in_sizes[0] / HID;
    int b   = in_sizes[10] - 1;
    int s   = nnz / b;

    float *q, *kt, *vt, *kg, *vg, *attn;
    cudaGetSymbolAddress((void**)&q,    g_q);
    cudaGetSymbolAddress((void**)&kt,   g_kt);
    cudaGetSymbolAddress((void**)&vt,   g_vt);
    cudaGetSymbolAddress((void**)&kg,   g_kg);
    cudaGetSymbolAddress((void**)&vg,   g_vg);
    cudaGetSymbolAddress((void**)&attn, g_attn);

    __nv_bfloat16 *hsh, *hsl, *wqh, *wql, *wkh, *wkl;
    __half *hsh16, *hsl16, *wvh16, *woh, *ath;
    cudaGetSymbolAddress((void**)&hsh,   g_hs_hi);
    cudaGetSymbolAddress((void**)&hsl,   g_hs_lo);
    cudaGetSymbolAddress((void**)&wqh,   g_wq_hi);
    cudaGetSymbolAddress((void**)&wql,   g_wq_lo);
    cudaGetSymbolAddress((void**)&wkh,   g_wk_hi);
    cudaGetSymbolAddress((void**)&wkl,   g_wk_lo);
    cudaGetSymbolAddress((void**)&hsh16, g_hs_h16);
    cudaGetSymbolAddress((void**)&hsl16, g_hs_l16);
    cudaGetSymbolAddress((void**)&wvh16, g_wv_h);
    cudaGetSymbolAddress((void**)&woh,   g_wo_h);
    cudaGetSymbolAddress((void**)&ath,   g_at_h);

    const size_t ATTN_SMEM =
        (size_t)(128 * QPITCH + 64 * KPITCH + 128 * VPITCH + 128 * PPITCH) * sizeof(float);
    cudaFuncSetAttribute(attn_kernel, cudaFuncAttributeMaxDynamicSharedMemorySize,
                         (int)ATTN_SMEM);
    cudaFuncSetAttribute(qkv_gemm, cudaFuncAttributeMaxDynamicSharedMemorySize, GEMM_SMEM);
    cudaFuncSetAttribute(hgemm_o,  cudaFuncAttributeMaxDynamicSharedMemorySize, GEMM_SMEM);

    // 1. RoPE cos/sin table
    rope_table_kernel<<<s, 64>>>();

    // 2. converts
    {
        int n4;
        n4 = nnz * HID / 4;      cvt_split_kernel<<<(n4 + 255) / 256, 256>>>(hs, hsh, hsl, n4);
        n4 = nnz * HID / 4;      cvt_split_f16_kernel<<<(n4 + 255) / 256, 256>>>(hs, hsh16, hsl16, n4);
        n4 = NH  * HD * HID / 4; cvt_split_kernel<<<(n4 + 255) / 256, 256>>>(wq, wqh, wql, n4);
        n4 = NKV * HD * HID / 4; cvt_split_kernel<<<(n4 + 255) / 256, 256>>>(wk, wkh, wkl, n4);
        n4 = NKV * HD * HID / 4; cvt_f16_kernel<<<(n4 + 255) / 256, 256>>>(wv, wvh16, n4);
        n4 = HID * NH * HD / 4;  cvt_f16_kernel<<<(n4 + 255) / 256, 256>>>(wo, woh, n4);
    }

    // 3. fused Q/K/V projection (Q,K 3xbf16; V 2-term fp16)
    qkv_gemm<<<dim3(48, nnz / BM), 256, GEMM_SMEM>>>(hsh, hsl, wqh, wql, wkh, wkl,
                                                     hsh16, hsl16, wvh16, q, kt, vt);

    // 4. RoPE + paged-KV scatter
    rope_q_kernel<<<nnz, 256>>>(q, pos);
    ropekv_scatter_kernel<<<nnz, 256>>>(pos, s);

    // 5. causal GQA flash attention (fp32)
    float scale = 1.0f / sqrtf((float)HD);
    attn_kernel<<<dim3(s / 128, NH, b), 256, ATTN_SMEM>>>(q, kg, vg, attn, s, scale);

    // 6. output projection (1-term fp16, both operands rounded)
    {
        int n4 = nnz * NH * HD / 4;
        cvt_f16_kernel<<<(n4 + 255) / 256, 256>>>(attn, ath, n4);
    }
    hgemm_o<<<dim3(HID / BN, nnz / BM), 256, GEMM_SMEM>>>(ath, woh,
                                                          (float*)d_out, HID, NH * HD);
}

// round 16
// speedup vs baseline: 1.8540x; 1.3855x over previous
#include <cuda_runtime.h>
#include <cuda_bf16.h>
#include <cuda_fp16.h>
#include <math.h>
#include <stdint.h>

// ---------------- problem constants ----------------
#define HID 4096
#define NH  32
#define NKV 8
#define HD  128
#define MAX_NNZ 4096
#define MAX_S   1024

// ---------------- device scratch (no allocs allowed) ----------------
__device__ float g_q   [(size_t)MAX_NNZ * NH  * HD];   // fp32 Q from GEMM
__device__ float g_kt  [(size_t)MAX_NNZ * NKV * HD];   // fp32 K (token order)
__device__ float g_vt  [(size_t)MAX_NNZ * NKV * HD];   // fp32 V (token order)
__device__ float g_cos [MAX_S * 64];
__device__ float g_sin [MAX_S * 64];

// bf16 split operands (Q/K projections — softmax-amplified path)
__device__ __nv_bfloat16 g_hs_hi[(size_t)MAX_NNZ * HID];
__device__ __nv_bfloat16 g_hs_lo[(size_t)MAX_NNZ * HID];
__device__ __nv_bfloat16 g_wq_hi[(size_t)NH  * HD * HID];
__device__ __nv_bfloat16 g_wq_lo[(size_t)NH  * HD * HID];
__device__ __nv_bfloat16 g_wk_hi[(size_t)NKV * HD * HID];
__device__ __nv_bfloat16 g_wk_lo[(size_t)NKV * HD * HID];
// fp16 operands (V / O projections — direct path)
__device__ __half g_hs_h16[(size_t)MAX_NNZ * HID];
__device__ __half g_hs_l16[(size_t)MAX_NNZ * HID];
__device__ __half g_wv_h  [(size_t)NKV * HD * HID];
__device__ __half g_wo_h  [(size_t)HID * NH * HD];
__device__ __half g_at_h  [(size_t)MAX_NNZ * NH * HD];  // attention out (fp16)
// fp16 attention operands
__device__ __half g_qh16[(size_t)MAX_NNZ * NH  * HD];   // RoPE'd Q hi
__device__ __half g_ql16[(size_t)MAX_NNZ * NH  * HD];   // RoPE'd Q lo
__device__ __half g_kh16[(size_t)MAX_NNZ * NKV * HD];   // gathered RoPE'd K hi
__device__ __half g_kl16[(size_t)MAX_NNZ * NKV * HD];   // gathered RoPE'd K lo
__device__ __half g_vh16[(size_t)MAX_NNZ * NKV * HD];   // gathered V (rounded)

// ---------------- helpers ----------------
__device__ __forceinline__ uint32_t smem_u32(const void* p) {
    uint32_t a;
    asm("{ .reg .u64 t; cvta.to.shared.u64 t, %1; cvt.u32.u64 %0, t; }" : "=r"(a) : "l"(p));
    return a;
}
#define SWZ128(o) ((o) ^ (((o) >> 3) & 0x70))

__device__ __forceinline__ void mma16816(float* c, const uint32_t* a, const uint32_t* b) {
    asm volatile(
        "mma.sync.aligned.m16n8k16.row.col.f32.bf16.bf16.f32 "
        "{%0,%1,%2,%3}, {%4,%5,%6,%7}, {%8,%9}, {%0,%1,%2,%3};\n"
        : "+f"(c[0]), "+f"(c[1]), "+f"(c[2]), "+f"(c[3])
        : "r"(a[0]), "r"(a[1]), "r"(a[2]), "r"(a[3]), "r"(b[0]), "r"(b[1]));
}
__device__ __forceinline__ void mma16816h(float* c, const uint32_t* a, const uint32_t* b) {
    asm volatile(
        "mma.sync.aligned.m16n8k16.row.col.f32.f16.f16.f32 "
        "{%0,%1,%2,%3}, {%4,%5,%6,%7}, {%8,%9}, {%0,%1,%2,%3};\n"
        : "+f"(c[0]), "+f"(c[1]), "+f"(c[2]), "+f"(c[3])
        : "r"(a[0]), "r"(a[1]), "r"(a[2]), "r"(a[3]), "r"(b[0]), "r"(b[1]));
}
__device__ __forceinline__ void ldsm4(uint32_t* r, uint32_t addr) {
    asm volatile("ldmatrix.sync.aligned.m8n8.x4.shared.b16 {%0,%1,%2,%3}, [%4];"
        : "=r"(r[0]), "=r"(r[1]), "=r"(r[2]), "=r"(r[3]) : "r"(addr));
}
__device__ __forceinline__ void cp16(uint32_t dst, const void* src) {
    asm volatile("cp.async.cg.shared.global [%0], [%1], 16;" :: "r"(dst), "l"(src));
}
__device__ __forceinline__ uint32_t packh2(float a, float b) {
    __half2 h = __floats2half2_rn(a, b);
    return *(uint32_t*)&h;
}

// ---------------- converts ----------------
__global__ void cvt_split_kernel(const float* __restrict__ x,
                                 __nv_bfloat16* __restrict__ hi,
                                 __nv_bfloat16* __restrict__ lo, int n4) {
    int i = blockIdx.x * blockDim.x + threadIdx.x;
    if (i >= n4) return;
    float4 v = ((const float4*)x)[i];
    union { __nv_bfloat16 b[4]; uint2 u; } H, L;
    H.b[0] = __float2bfloat16_rn(v.x);
    H.b[1] = __float2bfloat16_rn(v.y);
    H.b[2] = __float2bfloat16_rn(v.z);
    H.b[3] = __float2bfloat16_rn(v.w);
    L.b[0] = __float2bfloat16_rn(v.x - __bfloat162float(H.b[0]));
    L.b[1] = __float2bfloat16_rn(v.y - __bfloat162float(H.b[1]));
    L.b[2] = __float2bfloat16_rn(v.z - __bfloat162float(H.b[2]));
    L.b[3] = __float2bfloat16_rn(v.w - __bfloat162float(H.b[3]));
    ((uint2*)hi)[i] = H.u;
    ((uint2*)lo)[i] = L.u;
}

// dual split: one read of x -> bf16 hi/lo + fp16 hi/lo
__global__ void cvt_split_dual_kernel(const float* __restrict__ x,
                                      __nv_bfloat16* __restrict__ bhi,
                                      __nv_bfloat16* __restrict__ blo,
                                      __half* __restrict__ hhi,
                                      __half* __restrict__ hlo, int n4) {
    int i = blockIdx.x * blockDim.x + threadIdx.x;
    if (i >= n4) return;
    float4 v = ((const float4*)x)[i];
    float f[4] = {v.x, v.y, v.z, v.w};
    union { __nv_bfloat16 b[4]; uint2 u; } BH, BL;
    union { __half h[4]; uint2 u; } HH, HL;
#pragma unroll
    for (int j = 0; j < 4; ++j) {
        BH.b[j] = __float2bfloat16_rn(f[j]);
        BL.b[j] = __float2bfloat16_rn(f[j] - __bfloat162float(BH.b[j]));
        HH.h[j] = __float2half_rn(f[j]);
        HL.h[j] = __float2half_rn(f[j] - __half2float(HH.h[j]));
    }
    ((uint2*)bhi)[i] = BH.u;
    ((uint2*)blo)[i] = BL.u;
    ((uint2*)hhi)[i] = HH.u;
    ((uint2*)hlo)[i] = HL.u;
}

__global__ void cvt_f16_kernel(const float* __restrict__ x,
                               __half* __restrict__ h, int n4) {
    int i = blockIdx.x * blockDim.x + threadIdx.x;
    if (i >= n4) return;
    float4 v = ((const float4*)x)[i];
    union { __half h[4]; uint2 u; } H;
    H.h[0] = __float2half_rn(v.x);
    H.h[1] = __float2half_rn(v.y);
    H.h[2] = __float2half_rn(v.z);
    H.h[3] = __float2half_rn(v.w);
    ((uint2*)h)[i] = H.u;
}

// ---------------- RoPE table ----------------
__global__ void rope_table_kernel() {
    int p = blockIdx.x;
    int j = threadIdx.x;
    double e    = (double)j / 64.0;
    double freq = exp(-e * log(500000.0));
    const double PI = 3.14159265358979323846;
    double wavelen = 2.0 * PI / freq;
    double f;
    if (wavelen < 2048.0)       f = freq;
    else if (wavelen > 8192.0)  f = freq / 8.0;
    else {
        double smooth = (8192.0 / wavelen - 1.0) / 3.0;
        f = (1.0 - smooth) * freq / 8.0 + smooth * freq;
    }
    double ang = (double)p * f;
    g_cos[p * 64 + j] = (float)cos(ang);
    g_sin[p * 64 + j] = (float)sin(ang);
}

// RoPE Q -> fp16 hi/lo split
__global__ void rope_q_kernel(const float* __restrict__ q, __half* __restrict__ qh,
                              __half* __restrict__ ql, const int* __restrict__ pos) {
    int i = blockIdx.x;
    int p = pos[i];
    const float* cr = g_cos + (size_t)p * 64;
    const float* sr = g_sin + (size_t)p * 64;
    const float* base = q + (size_t)i * (NH * HD);
    __half* oh = qh + (size_t)i * (NH * HD);
    __half* ol = ql + (size_t)i * (NH * HD);
    for (int idx = threadIdx.x; idx < NH * 64; idx += blockDim.x) {
        int h = idx >> 6, j = idx & 63;
        float c = cr[j], s = sr[j];
        float x1 = base[h * HD + j], x2 = base[h * HD + j + 64];
        float y1 = x1 * c - x2 * s;
        float y2 = x2 * c + x1 * s;
        __half h1 = __float2half_rn(y1);
        __half h2 = __float2half_rn(y2);
        oh[h * HD + j]      = h1;
        oh[h * HD + j + 64] = h2;
        ol[h * HD + j]      = __float2half_rn(y1 - __half2float(h1));
        ol[h * HD + j + 64] = __float2half_rn(y2 - __half2float(h2));
    }
}

// RoPE K + gather-scatter -> fp16 hi/lo; V -> fp16
__global__ void ropekv_scatter_kernel(const int* __restrict__ pos, int s_per_b) {
    int i = blockIdx.x;
    int b = i / s_per_b;
    int p = pos[i];
    int dst = b * s_per_b + p;
    const float* cr = g_cos + (size_t)p * 64;
    const float* sr = g_sin + (size_t)p * 64;
    const float* kin = g_kt + (size_t)i * (NKV * HD);
    __half* kh = g_kh16 + (size_t)dst * (NKV * HD);
    __half* kl = g_kl16 + (size_t)dst * (NKV * HD);
    for (int idx = threadIdx.x; idx < NKV * 64; idx += blockDim.x) {
        int h = idx >> 6, j = idx & 63;
        float c = cr[j], s = sr[j];
        float x1 = kin[h * HD + j], x2 = kin[h * HD + j + 64];
        float y1 = x1 * c - x2 * s;
        float y2 = x2 * c + x1 * s;
        __half h1 = __float2half_rn(y1);
        __half h2 = __float2half_rn(y2);
        kh[h * HD + j]      = h1;
        kh[h * HD + j + 64] = h2;
        kl[h * HD + j]      = __float2half_rn(y1 - __half2float(h1));
        kl[h * HD + j + 64] = __float2half_rn(y2 - __half2float(h2));
    }
    const float* vin = g_vt + (size_t)i * (NKV * HD);
    __half* vo = g_vh16 + (size_t)dst * (NKV * HD);
    for (int idx = threadIdx.x; idx < NKV * HD; idx += blockDim.x)
        vo[idx] = __float2half_rn(vin[idx]);
}

// ================= GEMM cores =================
#define BM 128
#define BN 128
#define BK 64
#define NSTAGE   3
#define ST_BYTES (64 * 1024)
#define OFF_AH   0
#define OFF_AL   (16 * 1024)
#define OFF_BH   (32 * 1024)
#define OFF_BL   (48 * 1024)
#define GEMM_SMEM (NSTAGE * ST_BYTES)

__device__ __forceinline__ void load_stage(
    uint32_t sb, int tid,
    const __nv_bfloat16* __restrict__ Ahi, const __nv_bfloat16* __restrict__ Alo,
    const __nv_bfloat16* __restrict__ Bhi, const __nv_bfloat16* __restrict__ Blo,
    int m0, int n0, int K, int k0) {
#pragma unroll
    for (int i = 0; i < 4; ++i) {
        int idx = tid + i * 256;
        int r = idx >> 3, c = idx & 7;
        uint32_t off = SWZ128((uint32_t)(r * 128 + c * 16));
        const size_t ga = (size_t)(m0 + r) * K + k0 + c * 8;
        cp16(sb + OFF_AH + off, Ahi + ga);
        cp16(sb + OFF_AL + off, Alo + ga);
        const size_t gb = (size_t)(n0 + r) * K + k0 + c * 8;
        cp16(sb + OFF_BH + off, Bhi + gb);
        cp16(sb + OFF_BL + off, Blo + gb);
    }
    asm volatile("cp.async.commit_group;" ::: "memory");
}

__device__ __forceinline__ void gemm_core(
    uint32_t smb,
    const __nv_bfloat16* __restrict__ Ahi, const __nv_bfloat16* __restrict__ Alo,
    const __nv_bfloat16* __restrict__ Bhi, const __nv_bfloat16* __restrict__ Blo,
    float* __restrict__ C, int m0, int n0, int N, int K) {
    const int tid  = threadIdx.x;
    const int wid  = tid >> 5;
    const int lane = tid & 31;
    const int wm = (wid & 3) << 5;
    const int wn = (wid >> 2) << 6;

    const int a_row0 = wm + (lane & 15);
    const int a_csel = lane >> 4;
    const int b_row0 = wn + (lane & 7) + ((lane >> 4) << 3);
    const int b_csel = (lane >> 3) & 1;

    float acc[2][8][4];
#pragma unroll
    for (int mi = 0; mi < 2; ++mi)
#pragma unroll
        for (int ni = 0; ni < 8; ++ni)
#pragma unroll
            for (int r = 0; r < 4; ++r) acc[mi][ni][r] = 0.f;

    const int NIT = K / BK;
    load_stage(smb + 0 * ST_BYTES, tid, Ahi, Alo, Bhi, Blo, m0, n0, K, 0);
    if (NIT > 1)
        load_stage(smb + 1 * ST_BYTES, tid, Ahi, Alo, Bhi, Blo, m0, n0, K, BK);

    int buf = 0;
    for (int it = 0; it < NIT; ++it) {
        if (it + 1 < NIT) asm volatile("cp.async.wait_group 1;" ::: "memory");
        else              asm volatile("cp.async.wait_group 0;" ::: "memory");
        __syncthreads();

        if (it + 2 < NIT) {
            int nb = buf + 2; if (nb >= NSTAGE) nb -= NSTAGE;
            load_stage(smb + nb * ST_BYTES, tid, Ahi, Alo, Bhi, Blo, m0, n0, K, (it + 2) * BK);
        }

        const uint32_t sb = smb + buf * ST_BYTES;
#pragma unroll
        for (int ks = 0; ks < 4; ++ks) {
            const int kc = ks * 2;
            uint32_t ah[2][4], al[2][4], bh[4][4], bl[4][4];
#pragma unroll
            for (int mi = 0; mi < 2; ++mi) {
                uint32_t off = SWZ128((uint32_t)((a_row0 + mi * 16) * 128 + (kc + a_csel) * 16));
                ldsm4(ah[mi], sb + OFF_AH + off);
                ldsm4(al[mi], sb + OFF_AL + off);
            }
#pragma unroll
            for (int ni2 = 0; ni2 < 4; ++ni2) {
                uint32_t off = SWZ128((uint32_t)((b_row0 + ni2 * 16) * 128 + (kc + b_csel) * 16));
                ldsm4(bh[ni2], sb + OFF_BH + off);
                ldsm4(bl[ni2], sb + OFF_BL + off);
            }
#pragma unroll
            for (int ni = 0; ni < 8; ++ni)
#pragma unroll
                for (int mi = 0; mi < 2; ++mi)
                    mma16816(acc[mi][ni], ah[mi], &bh[ni >> 1][(ni & 1) * 2]);
#pragma unroll
            for (int ni = 0; ni < 8; ++ni)
#pragma unroll
                for (int mi = 0; mi < 2; ++mi)
                    mma16816(acc[mi][ni], ah[mi], &bl[ni >> 1][(ni & 1) * 2]);
#pragma unroll
            for (int ni = 0; ni < 8; ++ni)
#pragma unroll
                for (int mi = 0; mi < 2; ++mi)
                    mma16816(acc[mi][ni], al[mi], &bh[ni >> 1][(ni & 1) * 2]);
        }
        if (++buf == NSTAGE) buf = 0;
    }

    const int gid = lane >> 2, tig = lane & 3;
#pragma unroll
    for (int mi = 0; mi < 2; ++mi) {
#pragma unroll
        for (int ni = 0; ni < 8; ++ni) {
            const int row = m0 + wm + mi * 16 + gid;
            const int col = n0 + wn + ni * 8 + 2 * tig;
            *(float2*)&C[(size_t)row * N + col] =
                make_float2(acc[mi][ni][0], acc[mi][ni][1]);
            *(float2*)&C[(size_t)(row + 8) * N + col] =
                make_float2(acc[mi][ni][2], acc[mi][ni][3]);
        }
    }
}

// fp16 core, NT terms (A in NT pieces, B rounded)
template <int NT>
__device__ __forceinline__ void gemm_core_f16(
    uint32_t smb,
    const __half* __restrict__ Ahi, const __half* __restrict__ Alo,
    const __half* __restrict__ Bh,
    float* __restrict__ C, __half* __restrict__ Ch,
    int m0, int n0, int N, int K) {
    constexpr uint32_t STB  = (NT == 2) ? 48 * 1024 : 32 * 1024;
    constexpr uint32_t OFFB = (NT == 2) ? 32 * 1024 : 16 * 1024;
    const int tid  = threadIdx.x;
    const int wid  = tid >> 5;
    const int lane = tid & 31;
    const int wm = (wid & 3) << 5;
    const int wn = (wid >> 2) << 6;

    const int a_row0 = wm + (lane & 15);
    const int a_csel = lane >> 4;
    const int b_row0 = wn + (lane & 7) + ((lane >> 4) << 3);
    const int b_csel = (lane >> 3) & 1;

    auto load_f16 = [&](uint32_t sb, int k0) {
#pragma unroll
        for (int i = 0; i < 4; ++i) {
            int idx = tid + i * 256;
            int r = idx >> 3, c = idx & 7;
            uint32_t off = SWZ128((uint32_t)(r * 128 + c * 16));
            const size_t ga = (size_t)(m0 + r) * K + k0 + c * 8;
            cp16(sb + off, Ahi + ga);
            if (NT == 2) cp16(sb + 16 * 1024 + off, Alo + ga);
            const size_t gb = (size_t)(n0 + r) * K + k0 + c * 8;
            cp16(sb + OFFB + off, Bh + gb);
        }
        asm volatile("cp.async.commit_group;" ::: "memory");
    };

    float acc[2][8][4];
#pragma unroll
    for (int mi = 0; mi < 2; ++mi)
#pragma unroll
        for (int ni = 0; ni < 8; ++ni)
#pragma unroll
            for (int r = 0; r < 4; ++r) acc[mi][ni][r] = 0.f;

    const int NIT = K / BK;
    load_f16(smb + 0 * STB, 0);
    if (NIT > 1) load_f16(smb + 1 * STB, BK);

    int buf = 0;
    for (int it = 0; it < NIT; ++it) {
        if (it + 1 < NIT) asm volatile("cp.async.wait_group 1;" ::: "memory");
        else              asm volatile("cp.async.wait_group 0;" ::: "memory");
        __syncthreads();

        if (it + 2 < NIT) {
            int nb = buf + 2; if (nb >= NSTAGE) nb -= NSTAGE;
            load_f16(smb + nb * STB, (it + 2) * BK);
        }

        const uint32_t sb = smb + buf * STB;
#pragma unroll
        for (int ks = 0; ks < 4; ++ks) {
            const int kc = ks * 2;
            uint32_t ah[2][4], al[2][4], bh[4][4];
#pragma unroll
            for (int mi = 0; mi < 2; ++mi) {
                uint32_t off = SWZ128((uint32_t)((a_row0 + mi * 16) * 128 + (kc + a_csel) * 16));
                ldsm4(ah[mi], sb + off);
                if (NT == 2) ldsm4(al[mi], sb + 16 * 1024 + off);
            }
#pragma unroll
            for (int ni2 = 0; ni2 < 4; ++ni2) {
                uint32_t off = SWZ128((uint32_t)((b_row0 + ni2 * 16) * 128 + (kc + b_csel) * 16));
                ldsm4(bh[ni2], sb + OFFB + off);
            }
#pragma unroll
            for (int ni = 0; ni < 8; ++ni)
#pragma unroll
                for (int mi = 0; mi < 2; ++mi)
                    mma16816h(acc[mi][ni], ah[mi], &bh[ni >> 1][(ni & 1) * 2]);
            if (NT == 2) {
#pragma unroll
                for (int ni = 0; ni < 8; ++ni)
#pragma unroll
                    for (int mi = 0; mi < 2; ++mi)
                        mma16816h(acc[mi][ni], al[mi], &bh[ni >> 1][(ni & 1) * 2]);
            }
        }
        if (++buf == NSTAGE) buf = 0;
    }

    const int gid = lane >> 2, tig = lane & 3;
#pragma unroll
    for (int mi = 0; mi < 2; ++mi) {
#pragma unroll
        for (int ni = 0; ni < 8; ++ni) {
            const int row = m0 + wm + mi * 16 + gid;
            const int col = n0 + wn + ni * 8 + 2 * tig;
            *(float2*)&C[(size_t)row * N + col] =
                make_float2(acc[mi][ni][0], acc[mi][ni][1]);
            *(float2*)&C[(size_t)(row + 8) * N + col] =
                make_float2(acc[mi][ni][2], acc[mi][ni][3]);
        }
    }
    (void)Ch;
}

// fused QKV projection: 48 n-blocks (32 Q | 8 K bf16 path, 8 V fp16 path)
__global__ __launch_bounds__(256, 1)
void qkv_gemm(const __nv_bfloat16* __restrict__ hsh, const __nv_bfloat16* __restrict__ hsl,
              const __nv_bfloat16* __restrict__ wqh, const __nv_bfloat16* __restrict__ wql,
              const __nv_bfloat16* __restrict__ wkh, const __nv_bfloat16* __restrict__ wkl,
              const __half* __restrict__ hsh16, const __half* __restrict__ hsl16,
              const __half* __restrict__ wvh16,
              float* __restrict__ q, float* __restrict__ kt, float* __restrict__ vt) {
    extern __shared__ char smc[];
    const uint32_t smb = smem_u32(smc);
    const int nb = blockIdx.x;
    const int m0 = blockIdx.y * BM;
    if (nb < 32) {
        gemm_core(smb, hsh, hsl, wqh, wql, q, m0, nb * 128, NH * HD, HID);
    } else if (nb < 40) {
        gemm_core(smb, hsh, hsl, wkh, wkl, kt, m0, (nb - 32) * 128, NKV * HD, HID);
    } else {
        gemm_core_f16<2>(smb, hsh16, hsl16, wvh16, vt, nullptr,
                         m0, (nb - 40) * 128, NKV * HD, HID);
    }
}

// O-projection: 1-term fp16
__global__ __launch_bounds__(256, 1)
void hgemm_o(const __half* __restrict__ Ah, const __half* __restrict__ Bh,
             float* __restrict__ C, int N, int K) {
    extern __shared__ char smc[];
    gemm_core_f16<1>(smem_u32(smc), Ah, (const __half*)nullptr, Bh, C, nullptr,
                     blockIdx.y * BM, blockIdx.x * BN, N, K);
}

// ================= HMMA flash attention =================
// CTA: (q-tile 128, head, batch); 256 threads = 8 warps, warp = 16 q-rows.
// QK^T: 3-term fp16 (amplified path); PV: 1-term fp16, S-frags reused as A-frags.
#define AQP 136          // Q/K smem pitch (fp16 elements)
#define AVP 72           // V^T smem pitch
#define AT_QH  0
#define AT_QL  (128 * AQP * 2)
#define AT_KH  (2 * 128 * AQP * 2)
#define AT_KL  (AT_KH + 64 * AQP * 2)
#define AT_VT  (AT_KL + 64 * AQP * 2)
#define ATTN_SMEM_B (AT_VT + 128 * AVP * 2)

__global__ __launch_bounds__(256, 1)
void attn_kernel(const __half* __restrict__ Qh, const __half* __restrict__ Ql,
                 const __half* __restrict__ Kh, const __half* __restrict__ Kl,
                 const __half* __restrict__ Vh, __half* __restrict__ O,
                 int S, float scale) {
    extern __shared__ char sma[];
    const uint32_t smb = smem_u32(sma);
    __half* VT = (__half*)(sma + AT_VT);

    const int qt = blockIdx.x, h = blockIdx.y, b = blockIdx.z;
    const int kvh = h / (NH / NKV);
    const int tid = threadIdx.x, wid = tid >> 5, lane = tid & 31;
    const int gid = lane >> 2, tig = lane & 3;
    const int q0 = qt * 128;

    // load Q hi/lo tiles: 128 rows x 16 chunks of 8 fp16
    for (int it = tid; it < 128 * 16; it += 256) {
        int r = it >> 4, ch = it & 15;
        size_t g = ((size_t)(b * S + q0 + r) * NH + h) * HD + ch * 8;
        *(uint4*)(sma + AT_QH + (r * AQP + ch * 8) * 2) = *(const uint4*)(Qh + g);
        *(uint4*)(sma + AT_QL + (r * AQP + ch * 8) * 2) = *(const uint4*)(Ql + g);
    }

    float m_i[2] = {-3.0e38f, -3.0e38f}, l_i[2] = {0.f, 0.f};
    float oacc[16][4];
#pragma unroll
    for (int nj = 0; nj < 16; ++nj)
#pragma unroll
        for (int r = 0; r < 4; ++r) oacc[nj][r] = 0.f;

    const int a_row0 = wid * 16 + (lane & 15);
    const int a_csel = lane >> 4;
    const int b_row0 = (lane & 7) + ((lane >> 4) << 3);
    const int b_csel = (lane >> 3) & 1;
    const int qrow0 = q0 + wid * 16 + gid;
    const int qrow1 = qrow0 + 8;

    const int ntiles = (q0 + 128) >> 6;
    for (int t = 0; t < ntiles; ++t) {
        const int kv0 = t * 64;
        __syncthreads();
        // load K hi/lo + V^T
        for (int it = tid; it < 64 * 16; it += 256) {
            int c = it >> 4, ch = it & 15;
            size_t g = ((size_t)(b * S + kv0 + c) * NKV + kvh) * HD + ch * 8;
            *(uint4*)(sma + AT_KH + (c * AQP + ch * 8) * 2) = *(const uint4*)(Kh + g);
            *(uint4*)(sma + AT_KL + (c * AQP + ch * 8) * 2) = *(const uint4*)(Kl + g);
            uint4 vv = *(const uint4*)(Vh + g);
            const __half* vp = (const __half*)&vv;
            int d = ch * 8;
#pragma unroll
            for (int j = 0; j < 8; ++j)
                VT[(d + j) * AVP + c] = vp[j];
        }
        __syncthreads();

        // ---- S = Q K^T (3-term fp16) ----
        float sacc[8][4];
#pragma unroll
        for (int ni = 0; ni < 8; ++ni)
#pragma unroll
            for (int r = 0; r < 4; ++r) sacc[ni][r] = 0.f;
#pragma unroll
        for (int kc = 0; kc < 8; ++kc) {
            uint32_t ah[4], al[4], bh[4][4], bl[4][4];
            uint32_t aoff = (uint32_t)((a_row0 * AQP + (2 * kc + a_csel) * 8) * 2);
            ldsm4(ah, smb + AT_QH + aoff);
            ldsm4(al, smb + AT_QL + aoff);
#pragma unroll
            for (int n2 = 0; n2 < 4; ++n2) {
                uint32_t boff = (uint32_t)(((n2 * 16 + b_row0) * AQP + (2 * kc + b_csel) * 8) * 2);
                ldsm4(bh[n2], smb + AT_KH + boff);
                ldsm4(bl[n2], smb + AT_KL + boff);
            }
#pragma unroll
            for (int ni = 0; ni < 8; ++ni)
                mma16816h(sacc[ni], ah, &bh[ni >> 1][(ni & 1) * 2]);
#pragma unroll
            for (int ni = 0; ni < 8; ++ni)
                mma16816h(sacc[ni], ah, &bl[ni >> 1][(ni & 1) * 2]);
#pragma unroll
            for (int ni = 0; ni < 8; ++ni)
                mma16816h(sacc[ni], al, &bh[ni >> 1][(ni & 1) * 2]);
        }

        // ---- mask + online softmax ----
        float mx0 = -3.0e38f, mx1 = -3.0e38f;
#pragma unroll
        for (int ni = 0; ni < 8; ++ni) {
            int col = kv0 + ni * 8 + 2 * tig;
            sacc[ni][0] = (col     <= qrow0) ? sacc[ni][0] * scale : -1.0e30f;
            sacc[ni][1] = (col + 1 <= qrow0) ? sacc[ni][1] * scale : -1.0e30f;
            sacc[ni][2] = (col     <= qrow1) ? sacc[ni][2] * scale : -1.0e30f;
            sacc[ni][3] = (col + 1 <= qrow1) ? sacc[ni][3] * scale : -1.0e30f;
            mx0 = fmaxf(mx0, fmaxf(sacc[ni][0], sacc[ni][1]));
            mx1 = fmaxf(mx1, fmaxf(sacc[ni][2], sacc[ni][3]));
        }
        mx0 = fmaxf(mx0, __shfl_xor_sync(0xffffffffu, mx0, 1));
        mx0 = fmaxf(mx0, __shfl_xor_sync(0xffffffffu, mx0, 2));
        mx1 = fmaxf(mx1, __shfl_xor_sync(0xffffffffu, mx1, 1));
        mx1 = fmaxf(mx1, __shfl_xor_sync(0xffffffffu, mx1, 2));
        float mn0 = fmaxf(m_i[0], mx0);
        float mn1 = fmaxf(m_i[1], mx1);
        float al0 = __expf(m_i[0] - mn0);
        float al1 = __expf(m_i[1] - mn1);
        float ls0 = 0.f, ls1 = 0.f;
#pragma unroll
        for (int ni = 0; ni < 8; ++ni) {
            sacc[ni][0] = __expf(sacc[ni][0] - mn0);
            sacc[ni][1] = __expf(sacc[ni][1] - mn0);
            sacc[ni][2] = __expf(sacc[ni][2] - mn1);
            sacc[ni][3] = __expf(sacc[ni][3] - mn1);
            ls0 += sacc[ni][0] + sacc[ni][1];
            ls1 += sacc[ni][2] + sacc[ni][3];
        }
        ls0 += __shfl_xor_sync(0xffffffffu, ls0, 1);
        ls0 += __shfl_xor_sync(0xffffffffu, ls0, 2);
        ls1 += __shfl_xor_sync(0xffffffffu, ls1, 1);
        ls1 += __shfl_xor_sync(0xffffffffu, ls1, 2);
        l_i[0] = l_i[0] * al0 + ls0;
        l_i[1] = l_i[1] * al1 + ls1;
        m_i[0] = mn0;
        m_i[1] = mn1;
#pragma unroll
        for (int nj = 0; nj < 16; ++nj) {
            oacc[nj][0] *= al0; oacc[nj][1] *= al0;
            oacc[nj][2] *= al1; oacc[nj][3] *= al1;
        }

        // ---- O += P V: S-frags become A-frags directly ----
#pragma unroll
        for (int kc2 = 0; kc2 < 4; ++kc2) {
            uint32_t pa[4];
            pa[0] = packh2(sacc[2 * kc2][0],     sacc[2 * kc2][1]);
            pa[1] = packh2(sacc[2 * kc2][2],     sacc[2 * kc2][3]);
            pa[2] = packh2(sacc[2 * kc2 + 1][0], sacc[2 * kc2 + 1][1]);
            pa[3] = packh2(sacc[2 * kc2 + 1][2], sacc[2 * kc2 + 1][3]);
            uint32_t vb[8][4];
#pragma unroll
            for (int n2 = 0; n2 < 8; ++n2) {
                uint32_t boff = (uint32_t)(((n2 * 16 + b_row0) * AVP + (2 * kc2 + b_csel) * 8) * 2);
                ldsm4(vb[n2], smb + AT_VT + boff);
            }
#pragma unroll
            for (int nj = 0; nj < 16; ++nj)
                mma16816h(oacc[nj], pa, &vb[nj >> 1][(nj & 1) * 2]);
        }
    }

    // ---- epilogue: write fp16 attention output ----
    float inv0 = 1.f / l_i[0];
    float inv1 = 1.f / l_i[1];
    const int r0 = q0 + wid * 16 + gid;
    __half* op0 = O + ((size_t)(b * S + r0) * NH + h) * HD;
    __half* op1 = O + ((size_t)(b * S + r0 + 8) * NH + h) * HD;
#pragma unroll
    for (int nj = 0; nj < 16; ++nj) {
        int col = nj * 8 + 2 * tig;
        *(uint32_t*)(op0 + col) = packh2(oacc[nj][0] * inv0, oacc[nj][1] * inv0);
        *(uint32_t*)(op1 + col) = packh2(oacc[nj][2] * inv1, oacc[nj][3] * inv1);
    }
}

// ---------------- launch ----------------
extern "C" void kernel_launch(void* const* d_in, const int* in_sizes, int n_in,
                              void* d_out, int out_size) {
    const float* hs  = (const float*)d_in[0];
    const float* wq  = (const float*)d_in[1];
    const float* wk  = (const float*)d_in[2];
    const float* wv  = (const float*)d_in[3];
    const float* wo  = (const float*)d_in[4];
    const int*   pos = (const int*)  d_in[6];

    int nnz = in_sizes[0] / HID;
    int b   = in_sizes[10] - 1;
    int s   = nnz / b;

    float *q, *kt, *vt;
    cudaGetSymbolAddress((void**)&q,  g_q);
    cudaGetSymbolAddress((void**)&kt, g_kt);
    cudaGetSymbolAddress((void**)&vt, g_vt);

    __nv_bfloat16 *hsh, *hsl, *wqh, *wql, *wkh, *wkl;
    __half *hsh16, *hsl16, *wvh16, *woh, *ath;
    __half *qh16, *ql16, *kh16, *kl16, *vh16;
    cudaGetSymbolAddress((void**)&hsh,   g_hs_hi);
    cudaGetSymbolAddress((void**)&hsl,   g_hs_lo);
    cudaGetSymbolAddress((void**)&wqh,   g_wq_hi);
    cudaGetSymbolAddress((void**)&wql,   g_wq_lo);
    cudaGetSymbolAddress((void**)&wkh,   g_wk_hi);
    cudaGetSymbolAddress((void**)&wkl,   g_wk_lo);
    cudaGetSymbolAddress((void**)&hsh16, g_hs_h16);
    cudaGetSymbolAddress((void**)&hsl16, g_hs_l16);
    cudaGetSymbolAddress((void**)&wvh16, g_wv_h);
    cudaGetSymbolAddress((void**)&woh,   g_wo_h);
    cudaGetSymbolAddress((void**)&ath,   g_at_h);
    cudaGetSymbolAddress((void**)&qh16,  g_qh16);
    cudaGetSymbolAddress((void**)&ql16,  g_ql16);
    cudaGetSymbolAddress((void**)&kh16,  g_kh16);
    cudaGetSymbolAddress((void**)&kl16,  g_kl16);
    cudaGetSymbolAddress((void**)&vh16,  g_vh16);

    cudaFuncSetAttribute(attn_kernel, cudaFuncAttributeMaxDynamicSharedMemorySize,
                         ATTN_SMEM_B);
    cudaFuncSetAttribute(qkv_gemm, cudaFuncAttributeMaxDynamicSharedMemorySize, GEMM_SMEM);
    cudaFuncSetAttribute(hgemm_o,  cudaFuncAttributeMaxDynamicSharedMemorySize, GEMM_SMEM);

    // 1. RoPE cos/sin table
    rope_table_kernel<<<s, 64>>>();

    // 2. converts (hs: single read -> both bf16 and fp16 splits)
    {
        int n4;
        n4 = nnz * HID / 4;
        cvt_split_dual_kernel<<<(n4 + 255) / 256, 256>>>(hs, hsh, hsl, hsh16, hsl16, n4);
        n4 = NH  * HD * HID / 4; cvt_split_kernel<<<(n4 + 255) / 256, 256>>>(wq, wqh, wql, n4);
        n4 = NKV * HD * HID / 4; cvt_split_kernel<<<(n4 + 255) / 256, 256>>>(wk, wkh, wkl, n4);
        n4 = NKV * HD * HID / 4; cvt_f16_kernel<<<(n4 + 255) / 256, 256>>>(wv, wvh16, n4);
        n4 = HID * NH * HD / 4;  cvt_f16_kernel<<<(n4 + 255) / 256, 256>>>(wo, woh, n4);
    }

    // 3. fused Q/K/V projection (Q,K 3xbf16; V 2-term fp16)
    qkv_gemm<<<dim3(48, nnz / BM), 256, GEMM_SMEM>>>(hsh, hsl, wqh, wql, wkh, wkl,
                                                     hsh16, hsl16, wvh16, q, kt, vt);

    // 4. RoPE -> fp16 splits + paged-KV gather-scatter
    rope_q_kernel<<<nnz, 256>>>(q, qh16, ql16, pos);
    ropekv_scatter_kernel<<<nnz, 256>>>(pos, s);

    // 5. HMMA flash attention (3-term fp16 QK^T, fp16 PV) -> fp16 out
    float scale = 1.0f / sqrtf((float)HD);
    attn_kernel<<<dim3(s / 128, NH, b), 256, ATTN_SMEM_B>>>(qh16, ql16, kh16, kl16,
                                                            vh16, ath, s, scale);

    // 6. output projection (1-term fp16)
    hgemm_o<<<dim3(HID / BN, nnz / BM), 256, GEMM_SMEM>>>(ath, woh,
                                                          (float*)d_out, HID, NH * HD);
}

// round 17
// speedup vs baseline: 1.9514x; 1.0526x over previous
#include <cuda_runtime.h>
#include <cuda_bf16.h>
#include <cuda_fp16.h>
#include <math.h>
#include <stdint.h>

// ---------------- problem constants ----------------
#define HID 4096
#define NH  32
#define NKV 8
#define HD  128
#define MAX_NNZ 4096
#define MAX_S   1024

// ---------------- device scratch (no allocs allowed) ----------------
__device__ float g_q   [(size_t)MAX_NNZ * NH  * HD];   // fp32 Q from GEMM
__device__ float g_kt  [(size_t)MAX_NNZ * NKV * HD];   // fp32 K (token order)
__device__ float g_vt  [(size_t)MAX_NNZ * NKV * HD];   // fp32 V (token order)
__device__ float g_cos [MAX_S * 64];
__device__ float g_sin [MAX_S * 64];

// bf16 split operands (Q/K projections — softmax-amplified path)
__device__ __nv_bfloat16 g_hs_hi[(size_t)MAX_NNZ * HID];
__device__ __nv_bfloat16 g_hs_lo[(size_t)MAX_NNZ * HID];
__device__ __nv_bfloat16 g_wq_hi[(size_t)NH  * HD * HID];
__device__ __nv_bfloat16 g_wq_lo[(size_t)NH  * HD * HID];
__device__ __nv_bfloat16 g_wk_hi[(size_t)NKV * HD * HID];
__device__ __nv_bfloat16 g_wk_lo[(size_t)NKV * HD * HID];
// fp16 operands (V / O projections — direct path)
__device__ __half g_hs_h16[(size_t)MAX_NNZ * HID];
__device__ __half g_wv_h  [(size_t)NKV * HD * HID];
__device__ __half g_wo_h  [(size_t)HID * NH * HD];
__device__ __half g_at_h  [(size_t)MAX_NNZ * NH * HD];  // attention out (fp16)
// fp16 attention operands
__device__ __half g_qh16[(size_t)MAX_NNZ * NH  * HD];
__device__ __half g_ql16[(size_t)MAX_NNZ * NH  * HD];
__device__ __half g_kh16[(size_t)MAX_NNZ * NKV * HD];
__device__ __half g_kl16[(size_t)MAX_NNZ * NKV * HD];
__device__ __half g_vh16[(size_t)MAX_NNZ * NKV * HD];

// ---------------- helpers ----------------
__device__ __forceinline__ uint32_t smem_u32(const void* p) {
    uint32_t a;
    asm("{ .reg .u64 t; cvta.to.shared.u64 t, %1; cvt.u32.u64 %0, t; }" : "=r"(a) : "l"(p));
    return a;
}
#define SWZ128(o) ((o) ^ (((o) >> 3) & 0x70))

__device__ __forceinline__ void mma16816(float* c, const uint32_t* a, const uint32_t* b) {
    asm volatile(
        "mma.sync.aligned.m16n8k16.row.col.f32.bf16.bf16.f32 "
        "{%0,%1,%2,%3}, {%4,%5,%6,%7}, {%8,%9}, {%0,%1,%2,%3};\n"
        : "+f"(c[0]), "+f"(c[1]), "+f"(c[2]), "+f"(c[3])
        : "r"(a[0]), "r"(a[1]), "r"(a[2]), "r"(a[3]), "r"(b[0]), "r"(b[1]));
}
__device__ __forceinline__ void mma16816h(float* c, const uint32_t* a, const uint32_t* b) {
    asm volatile(
        "mma.sync.aligned.m16n8k16.row.col.f32.f16.f16.f32 "
        "{%0,%1,%2,%3}, {%4,%5,%6,%7}, {%8,%9}, {%0,%1,%2,%3};\n"
        : "+f"(c[0]), "+f"(c[1]), "+f"(c[2]), "+f"(c[3])
        : "r"(a[0]), "r"(a[1]), "r"(a[2]), "r"(a[3]), "r"(b[0]), "r"(b[1]));
}
__device__ __forceinline__ void ldsm4(uint32_t* r, uint32_t addr) {
    asm volatile("ldmatrix.sync.aligned.m8n8.x4.shared.b16 {%0,%1,%2,%3}, [%4];"
        : "=r"(r[0]), "=r"(r[1]), "=r"(r[2]), "=r"(r[3]) : "r"(addr));
}
__device__ __forceinline__ void cp16(uint32_t dst, const void* src) {
    asm volatile("cp.async.cg.shared.global [%0], [%1], 16;" :: "r"(dst), "l"(src));
}
__device__ __forceinline__ uint32_t packh2(float a, float b) {
    __half2 h = __floats2half2_rn(a, b);
    return *(uint32_t*)&h;
}

// ---------------- converts ----------------
__global__ void cvt_split_kernel(const float* __restrict__ x,
                                 __nv_bfloat16* __restrict__ hi,
                                 __nv_bfloat16* __restrict__ lo, int n4) {
    int i = blockIdx.x * blockDim.x + threadIdx.x;
    if (i >= n4) return;
    float4 v = ((const float4*)x)[i];
    union { __nv_bfloat16 b[4]; uint2 u; } H, L;
    H.b[0] = __float2bfloat16_rn(v.x);
    H.b[1] = __float2bfloat16_rn(v.y);
    H.b[2] = __float2bfloat16_rn(v.z);
    H.b[3] = __float2bfloat16_rn(v.w);
    L.b[0] = __float2bfloat16_rn(v.x - __bfloat162float(H.b[0]));
    L.b[1] = __float2bfloat16_rn(v.y - __bfloat162float(H.b[1]));
    L.b[2] = __float2bfloat16_rn(v.z - __bfloat162float(H.b[2]));
    L.b[3] = __float2bfloat16_rn(v.w - __bfloat162float(H.b[3]));
    ((uint2*)hi)[i] = H.u;
    ((uint2*)lo)[i] = L.u;
}

// tri-output: one read of hs -> bf16 hi/lo (Q/K path) + fp16 rounded (V path)
__global__ void cvt_split_tri_kernel(const float* __restrict__ x,
                                     __nv_bfloat16* __restrict__ bhi,
                                     __nv_bfloat16* __restrict__ blo,
                                     __half* __restrict__ hhi, int n4) {
    int i = blockIdx.x * blockDim.x + threadIdx.x;
    if (i >= n4) return;
    float4 v = ((const float4*)x)[i];
    float f[4] = {v.x, v.y, v.z, v.w};
    union { __nv_bfloat16 b[4]; uint2 u; } BH, BL;
    union { __half h[4]; uint2 u; } HH;
#pragma unroll
    for (int j = 0; j < 4; ++j) {
        BH.b[j] = __float2bfloat16_rn(f[j]);
        BL.b[j] = __float2bfloat16_rn(f[j] - __bfloat162float(BH.b[j]));
        HH.h[j] = __float2half_rn(f[j]);
    }
    ((uint2*)bhi)[i] = BH.u;
    ((uint2*)blo)[i] = BL.u;
    ((uint2*)hhi)[i] = HH.u;
}

__global__ void cvt_f16_kernel(const float* __restrict__ x,
                               __half* __restrict__ h, int n4) {
    int i = blockIdx.x * blockDim.x + threadIdx.x;
    if (i >= n4) return;
    float4 v = ((const float4*)x)[i];
    union { __half h[4]; uint2 u; } H;
    H.h[0] = __float2half_rn(v.x);
    H.h[1] = __float2half_rn(v.y);
    H.h[2] = __float2half_rn(v.z);
    H.h[3] = __float2half_rn(v.w);
    ((uint2*)h)[i] = H.u;
}

// ---------------- RoPE table ----------------
__global__ void rope_table_kernel() {
    int p = blockIdx.x;
    int j = threadIdx.x;
    double e    = (double)j / 64.0;
    double freq = exp(-e * log(500000.0));
    const double PI = 3.14159265358979323846;
    double wavelen = 2.0 * PI / freq;
    double f;
    if (wavelen < 2048.0)       f = freq;
    else if (wavelen > 8192.0)  f = freq / 8.0;
    else {
        double smooth = (8192.0 / wavelen - 1.0) / 3.0;
        f = (1.0 - smooth) * freq / 8.0 + smooth * freq;
    }
    double ang = (double)p * f;
    g_cos[p * 64 + j] = (float)cos(ang);
    g_sin[p * 64 + j] = (float)sin(ang);
}

// RoPE Q -> fp16 hi/lo split
__global__ void rope_q_kernel(const float* __restrict__ q, __half* __restrict__ qh,
                              __half* __restrict__ ql, const int* __restrict__ pos) {
    int i = blockIdx.x;
    int p = pos[i];
    const float* cr = g_cos + (size_t)p * 64;
    const float* sr = g_sin + (size_t)p * 64;
    const float* base = q + (size_t)i * (NH * HD);
    __half* oh = qh + (size_t)i * (NH * HD);
    __half* ol = ql + (size_t)i * (NH * HD);
    for (int idx = threadIdx.x; idx < NH * 64; idx += blockDim.x) {
        int h = idx >> 6, j = idx & 63;
        float c = cr[j], s = sr[j];
        float x1 = base[h * HD + j], x2 = base[h * HD + j + 64];
        float y1 = x1 * c - x2 * s;
        float y2 = x2 * c + x1 * s;
        __half h1 = __float2half_rn(y1);
        __half h2 = __float2half_rn(y2);
        oh[h * HD + j]      = h1;
        oh[h * HD + j + 64] = h2;
        ol[h * HD + j]      = __float2half_rn(y1 - __half2float(h1));
        ol[h * HD + j + 64] = __float2half_rn(y2 - __half2float(h2));
    }
}

// RoPE K + gather-scatter -> fp16 hi/lo; V -> fp16
__global__ void ropekv_scatter_kernel(const int* __restrict__ pos, int s_per_b) {
    int i = blockIdx.x;
    int b = i / s_per_b;
    int p = pos[i];
    int dst = b * s_per_b + p;
    const float* cr = g_cos + (size_t)p * 64;
    const float* sr = g_sin + (size_t)p * 64;
    const float* kin = g_kt + (size_t)i * (NKV * HD);
    __half* kh = g_kh16 + (size_t)dst * (NKV * HD);
    __half* kl = g_kl16 + (size_t)dst * (NKV * HD);
    for (int idx = threadIdx.x; idx < NKV * 64; idx += blockDim.x) {
        int h = idx >> 6, j = idx & 63;
        float c = cr[j], s = sr[j];
        float x1 = kin[h * HD + j], x2 = kin[h * HD + j + 64];
        float y1 = x1 * c - x2 * s;
        float y2 = x2 * c + x1 * s;
        __half h1 = __float2half_rn(y1);
        __half h2 = __float2half_rn(y2);
        kh[h * HD + j]      = h1;
        kh[h * HD + j + 64] = h2;
        kl[h * HD + j]      = __float2half_rn(y1 - __half2float(h1));
        kl[h * HD + j + 64] = __float2half_rn(y2 - __half2float(h2));
    }
    const float* vin = g_vt + (size_t)i * (NKV * HD);
    __half* vo = g_vh16 + (size_t)dst * (NKV * HD);
    for (int idx = threadIdx.x; idx < NKV * HD; idx += blockDim.x)
        vo[idx] = __float2half_rn(vin[idx]);
}

// ================= GEMM cores (BM=256, warp tile 64x64) =================
#define BM 256
#define BN 128
#define BK 64
// bf16 3-term stage: Ah 32K | Al 32K | Bh 16K | Bl 16K = 96KB, 2 stages
#define ST_BYTES  (96 * 1024)
#define OFF_AL    (32 * 1024)
#define OFF_BH    (64 * 1024)
#define OFF_BL    (80 * 1024)
#define GEMM_SMEM (2 * ST_BYTES)

// ---- 3xBF16 core (Q/K projections) ----
__device__ __forceinline__ void load_stage(
    uint32_t sb, int tid,
    const __nv_bfloat16* __restrict__ Ahi, const __nv_bfloat16* __restrict__ Alo,
    const __nv_bfloat16* __restrict__ Bhi, const __nv_bfloat16* __restrict__ Blo,
    int m0, int n0, int K, int k0) {
#pragma unroll
    for (int i = 0; i < 8; ++i) {             // A: 256 rows x 8 chunks(16B)
        int idx = tid + i * 256;
        int r = idx >> 3, c = idx & 7;
        uint32_t off = SWZ128((uint32_t)(r * 128 + c * 16));
        const size_t ga = (size_t)(m0 + r) * K + k0 + c * 8;
        cp16(sb + off, Ahi + ga);
        cp16(sb + OFF_AL + off, Alo + ga);
    }
#pragma unroll
    for (int i = 0; i < 4; ++i) {             // B: 128 rows x 8 chunks
        int idx = tid + i * 256;
        int r = idx >> 3, c = idx & 7;
        uint32_t off = SWZ128((uint32_t)(r * 128 + c * 16));
        const size_t gb = (size_t)(n0 + r) * K + k0 + c * 8;
        cp16(sb + OFF_BH + off, Bhi + gb);
        cp16(sb + OFF_BL + off, Blo + gb);
    }
    asm volatile("cp.async.commit_group;" ::: "memory");
}

__device__ __forceinline__ void gemm_core(
    uint32_t smb,
    const __nv_bfloat16* __restrict__ Ahi, const __nv_bfloat16* __restrict__ Alo,
    const __nv_bfloat16* __restrict__ Bhi, const __nv_bfloat16* __restrict__ Blo,
    float* __restrict__ C, int m0, int n0, int N, int K) {
    const int tid  = threadIdx.x;
    const int wid  = tid >> 5;
    const int lane = tid & 31;
    const int wm = (wid & 3) << 6;    // 0,64,128,192
    const int wn = (wid >> 2) << 6;   // 0,64

    const int a_row0 = wm + (lane & 15);
    const int a_csel = lane >> 4;
    const int b_row0 = wn + (lane & 7) + ((lane >> 4) << 3);
    const int b_csel = (lane >> 3) & 1;

    float acc[4][8][4];
#pragma unroll
    for (int mi = 0; mi < 4; ++mi)
#pragma unroll
        for (int ni = 0; ni < 8; ++ni)
#pragma unroll
            for (int r = 0; r < 4; ++r) acc[mi][ni][r] = 0.f;

    const int NIT = K / BK;
    load_stage(smb, tid, Ahi, Alo, Bhi, Blo, m0, n0, K, 0);

    for (int it = 0; it < NIT; ++it) {
        const int cur = it & 1;
        if (it + 1 < NIT) {
            load_stage(smb + (cur ^ 1) * ST_BYTES, tid, Ahi, Alo, Bhi, Blo,
                       m0, n0, K, (it + 1) * BK);
            asm volatile("cp.async.wait_group 1;" ::: "memory");
        } else {
            asm volatile("cp.async.wait_group 0;" ::: "memory");
        }
        __syncthreads();

        const uint32_t sb = smb + cur * ST_BYTES;
#pragma unroll
        for (int ks = 0; ks < 4; ++ks) {
            const int kc = ks * 2;
            uint32_t ah[4][4], al[4][4], bb[4][4];
#pragma unroll
            for (int mi = 0; mi < 4; ++mi) {
                uint32_t off = SWZ128((uint32_t)((a_row0 + mi * 16) * 128 + (kc + a_csel) * 16));
                ldsm4(ah[mi], sb + off);
                ldsm4(al[mi], sb + OFF_AL + off);
            }
#pragma unroll
            for (int n2 = 0; n2 < 4; ++n2) {
                uint32_t off = SWZ128((uint32_t)((b_row0 + n2 * 16) * 128 + (kc + b_csel) * 16));
                ldsm4(bb[n2], sb + OFF_BH + off);
            }
            // hh + lh on bh
#pragma unroll
            for (int ni = 0; ni < 8; ++ni)
#pragma unroll
                for (int mi = 0; mi < 4; ++mi)
                    mma16816(acc[mi][ni], ah[mi], &bb[ni >> 1][(ni & 1) * 2]);
#pragma unroll
            for (int ni = 0; ni < 8; ++ni)
#pragma unroll
                for (int mi = 0; mi < 4; ++mi)
                    mma16816(acc[mi][ni], al[mi], &bb[ni >> 1][(ni & 1) * 2]);
            // reload bl over bb, then hl
#pragma unroll
            for (int n2 = 0; n2 < 4; ++n2) {
                uint32_t off = SWZ128((uint32_t)((b_row0 + n2 * 16) * 128 + (kc + b_csel) * 16));
                ldsm4(bb[n2], sb + OFF_BL + off);
            }
#pragma unroll
            for (int ni = 0; ni < 8; ++ni)
#pragma unroll
                for (int mi = 0; mi < 4; ++mi)
                    mma16816(acc[mi][ni], ah[mi], &bb[ni >> 1][(ni & 1) * 2]);
        }
        __syncthreads();
    }

    const int gid = lane >> 2, tig = lane & 3;
#pragma unroll
    for (int mi = 0; mi < 4; ++mi) {
#pragma unroll
        for (int ni = 0; ni < 8; ++ni) {
            const int row = m0 + wm + mi * 16 + gid;
            const int col = n0 + wn + ni * 8 + 2 * tig;
            *(float2*)&C[(size_t)row * N + col] =
                make_float2(acc[mi][ni][0], acc[mi][ni][1]);
            *(float2*)&C[(size_t)(row + 8) * N + col] =
                make_float2(acc[mi][ni][2], acc[mi][ni][3]);
        }
    }
}

// ---- fp16 core, NT terms (A in NT pieces, B rounded) ----
// stage: Ah 32K | (Al 32K if NT=2) | Bh 16K
template <int NT>
__device__ __forceinline__ void gemm_core_f16(
    uint32_t smb,
    const __half* __restrict__ Ahi, const __half* __restrict__ Alo,
    const __half* __restrict__ Bh,
    float* __restrict__ C, int m0, int n0, int N, int K) {
    constexpr uint32_t STB  = (NT == 2) ? 80 * 1024 : 48 * 1024;
    constexpr uint32_t OFFB = (NT == 2) ? 64 * 1024 : 32 * 1024;
    const int tid  = threadIdx.x;
    const int wid  = tid >> 5;
    const int lane = tid & 31;
    const int wm = (wid & 3) << 6;
    const int wn = (wid >> 2) << 6;

    const int a_row0 = wm + (lane & 15);
    const int a_csel = lane >> 4;
    const int b_row0 = wn + (lane & 7) + ((lane >> 4) << 3);
    const int b_csel = (lane >> 3) & 1;

    auto load_f16 = [&](uint32_t sb, int k0) {
#pragma unroll
        for (int i = 0; i < 8; ++i) {
            int idx = tid + i * 256;
            int r = idx >> 3, c = idx & 7;
            uint32_t off = SWZ128((uint32_t)(r * 128 + c * 16));
            const size_t ga = (size_t)(m0 + r) * K + k0 + c * 8;
            cp16(sb + off, Ahi + ga);
            if (NT == 2) cp16(sb + 32 * 1024 + off, Alo + ga);
        }
#pragma unroll
        for (int i = 0; i < 4; ++i) {
            int idx = tid + i * 256;
            int r = idx >> 3, c = idx & 7;
            uint32_t off = SWZ128((uint32_t)(r * 128 + c * 16));
            const size_t gb = (size_t)(n0 + r) * K + k0 + c * 8;
            cp16(sb + OFFB + off, Bh + gb);
        }
        asm volatile("cp.async.commit_group;" ::: "memory");
    };

    float acc[4][8][4];
#pragma unroll
    for (int mi = 0; mi < 4; ++mi)
#pragma unroll
        for (int ni = 0; ni < 8; ++ni)
#pragma unroll
            for (int r = 0; r < 4; ++r) acc[mi][ni][r] = 0.f;

    const int NIT = K / BK;
    load_f16(smb, 0);

    for (int it = 0; it < NIT; ++it) {
        const int cur = it & 1;
        if (it + 1 < NIT) {
            load_f16(smb + (cur ^ 1) * STB, (it + 1) * BK);
            asm volatile("cp.async.wait_group 1;" ::: "memory");
        } else {
            asm volatile("cp.async.wait_group 0;" ::: "memory");
        }
        __syncthreads();

        const uint32_t sb = smb + cur * STB;
#pragma unroll
        for (int ks = 0; ks < 4; ++ks) {
            const int kc = ks * 2;
            uint32_t ah[4][4], al[4][4], bb[4][4];
#pragma unroll
            for (int mi = 0; mi < 4; ++mi) {
                uint32_t off = SWZ128((uint32_t)((a_row0 + mi * 16) * 128 + (kc + a_csel) * 16));
                ldsm4(ah[mi], sb + off);
                if (NT == 2) ldsm4(al[mi], sb + 32 * 1024 + off);
            }
#pragma unroll
            for (int n2 = 0; n2 < 4; ++n2) {
                uint32_t off = SWZ128((uint32_t)((b_row0 + n2 * 16) * 128 + (kc + b_csel) * 16));
                ldsm4(bb[n2], sb + OFFB + off);
            }
#pragma unroll
            for (int ni = 0; ni < 8; ++ni)
#pragma unroll
                for (int mi = 0; mi < 4; ++mi)
                    mma16816h(acc[mi][ni], ah[mi], &bb[ni >> 1][(ni & 1) * 2]);
            if (NT == 2) {
#pragma unroll
                for (int ni = 0; ni < 8; ++ni)
#pragma unroll
                    for (int mi = 0; mi < 4; ++mi)
                        mma16816h(acc[mi][ni], al[mi], &bb[ni >> 1][(ni & 1) * 2]);
            }
        }
        __syncthreads();
    }

    const int gid = lane >> 2, tig = lane & 3;
#pragma unroll
    for (int mi = 0; mi < 4; ++mi) {
#pragma unroll
        for (int ni = 0; ni < 8; ++ni) {
            const int row = m0 + wm + mi * 16 + gid;
            const int col = n0 + wn + ni * 8 + 2 * tig;
            *(float2*)&C[(size_t)row * N + col] =
                make_float2(acc[mi][ni][0], acc[mi][ni][1]);
            *(float2*)&C[(size_t)(row + 8) * N + col] =
                make_float2(acc[mi][ni][2], acc[mi][ni][3]);
        }
    }
}

// fused QKV projection: 48 n-blocks (32 Q | 8 K 3xbf16; 8 V 1-term fp16)
__global__ __launch_bounds__(256, 1)
void qkv_gemm(const __nv_bfloat16* __restrict__ hsh, const __nv_bfloat16* __restrict__ hsl,
              const __nv_bfloat16* __restrict__ wqh, const __nv_bfloat16* __restrict__ wql,
              const __nv_bfloat16* __restrict__ wkh, const __nv_bfloat16* __restrict__ wkl,
              const __half* __restrict__ hsh16, const __half* __restrict__ wvh16,
              float* __restrict__ q, float* __restrict__ kt, float* __restrict__ vt) {
    extern __shared__ char smc[];
    const uint32_t smb = smem_u32(smc);
    const int nb = blockIdx.x;
    const int m0 = blockIdx.y * BM;
    if (nb < 32) {
        gemm_core(smb, hsh, hsl, wqh, wql, q, m0, nb * 128, NH * HD, HID);
    } else if (nb < 40) {
        gemm_core(smb, hsh, hsl, wkh, wkl, kt, m0, (nb - 32) * 128, NKV * HD, HID);
    } else {
        gemm_core_f16<1>(smb, hsh16, (const __half*)nullptr, wvh16, vt,
                         m0, (nb - 40) * 128, NKV * HD, HID);
    }
}

// O-projection: 1-term fp16
__global__ __launch_bounds__(256, 1)
void hgemm_o(const __half* __restrict__ Ah, const __half* __restrict__ Bh,
             float* __restrict__ C, int N, int K) {
    extern __shared__ char smc[];
    gemm_core_f16<1>(smem_u32(smc), Ah, (const __half*)nullptr, Bh, C,
                     blockIdx.y * BM, blockIdx.x * BN, N, K);
}

// ================= HMMA flash attention =================
// CTA: (q-tile 128, head, batch); 256 threads = 8 warps, warp = 16 q-rows.
// QK^T: 3-term fp16 (amplified path); PV: 1-term fp16, S-frags reused as A-frags.
#define AQP 136          // Q/K smem pitch (fp16 elements)
#define AVP 72           // V^T smem pitch
#define AT_QH  0
#define AT_QL  (128 * AQP * 2)
#define AT_KH  (2 * 128 * AQP * 2)
#define AT_KL  (AT_KH + 64 * AQP * 2)
#define AT_VT  (AT_KL + 64 * AQP * 2)
#define ATTN_SMEM_B (AT_VT + 128 * AVP * 2)

__global__ __launch_bounds__(256, 1)
void attn_kernel(const __half* __restrict__ Qh, const __half* __restrict__ Ql,
                 const __half* __restrict__ Kh, const __half* __restrict__ Kl,
                 const __half* __restrict__ Vh, __half* __restrict__ O,
                 int S, float scale) {
    extern __shared__ char sma[];
    const uint32_t smb = smem_u32(sma);
    __half* VT = (__half*)(sma + AT_VT);

    const int qt = blockIdx.x, h = blockIdx.y, b = blockIdx.z;
    const int kvh = h / (NH / NKV);
    const int tid = threadIdx.x, wid = tid >> 5, lane = tid & 31;
    const int gid = lane >> 2, tig = lane & 3;
    const int q0 = qt * 128;

    for (int it = tid; it < 128 * 16; it += 256) {
        int r = it >> 4, ch = it & 15;
        size_t g = ((size_t)(b * S + q0 + r) * NH + h) * HD + ch * 8;
        *(uint4*)(sma + AT_QH + (r * AQP + ch * 8) * 2) = *(const uint4*)(Qh + g);
        *(uint4*)(sma + AT_QL + (r * AQP + ch * 8) * 2) = *(const uint4*)(Ql + g);
    }

    float m_i[2] = {-3.0e38f, -3.0e38f}, l_i[2] = {0.f, 0.f};
    float oacc[16][4];
#pragma unroll
    for (int nj = 0; nj < 16; ++nj)
#pragma unroll
        for (int r = 0; r < 4; ++r) oacc[nj][r] = 0.f;

    const int a_row0 = wid * 16 + (lane & 15);
    const int a_csel = lane >> 4;
    const int b_row0 = (lane & 7) + ((lane >> 4) << 3);
    const int b_csel = (lane >> 3) & 1;
    const int qrow0 = q0 + wid * 16 + gid;
    const int qrow1 = qrow0 + 8;

    const int ntiles = (q0 + 128) >> 6;
    for (int t = 0; t < ntiles; ++t) {
        const int kv0 = t * 64;
        __syncthreads();
        for (int it = tid; it < 64 * 16; it += 256) {
            int c = it >> 4, ch = it & 15;
            size_t g = ((size_t)(b * S + kv0 + c) * NKV + kvh) * HD + ch * 8;
            *(uint4*)(sma + AT_KH + (c * AQP + ch * 8) * 2) = *(const uint4*)(Kh + g);
            *(uint4*)(sma + AT_KL + (c * AQP + ch * 8) * 2) = *(const uint4*)(Kl + g);
            uint4 vv = *(const uint4*)(Vh + g);
            const __half* vp = (const __half*)&vv;
            int d = ch * 8;
#pragma unroll
            for (int j = 0; j < 8; ++j)
                VT[(d + j) * AVP + c] = vp[j];
        }
        __syncthreads();

        // ---- S = Q K^T (3-term fp16) ----
        float sacc[8][4];
#pragma unroll
        for (int ni = 0; ni < 8; ++ni)
#pragma unroll
            for (int r = 0; r < 4; ++r) sacc[ni][r] = 0.f;
#pragma unroll
        for (int kc = 0; kc < 8; ++kc) {
            uint32_t ah[4], al[4], bh[4][4], bl[4][4];
            uint32_t aoff = (uint32_t)((a_row0 * AQP + (2 * kc + a_csel) * 8) * 2);
            ldsm4(ah, smb + AT_QH + aoff);
            ldsm4(al, smb + AT_QL + aoff);
#pragma unroll
            for (int n2 = 0; n2 < 4; ++n2) {
                uint32_t boff = (uint32_t)(((n2 * 16 + b_row0) * AQP + (2 * kc + b_csel) * 8) * 2);
                ldsm4(bh[n2], smb + AT_KH + boff);
                ldsm4(bl[n2], smb + AT_KL + boff);
            }
#pragma unroll
            for (int ni = 0; ni < 8; ++ni)
                mma16816h(sacc[ni], ah, &bh[ni >> 1][(ni & 1) * 2]);
#pragma unroll
            for (int ni = 0; ni < 8; ++ni)
                mma16816h(sacc[ni], ah, &bl[ni >> 1][(ni & 1) * 2]);
#pragma unroll
            for (int ni = 0; ni < 8; ++ni)
                mma16816h(sacc[ni], al, &bh[ni >> 1][(ni & 1) * 2]);
        }

        // ---- mask + online softmax ----
        float mx0 = -3.0e38f, mx1 = -3.0e38f;
#pragma unroll
        for (int ni = 0; ni < 8; ++ni) {
            int col = kv0 + ni * 8 + 2 * tig;
            sacc[ni][0] = (col     <= qrow0) ? sacc[ni][0] * scale : -1.0e30f;
            sacc[ni][1] = (col + 1 <= qrow0) ? sacc[ni][1] * scale : -1.0e30f;
            sacc[ni][2] = (col     <= qrow1) ? sacc[ni][2] * scale : -1.0e30f;
            sacc[ni][3] = (col + 1 <= qrow1) ? sacc[ni][3] * scale : -1.0e30f;
            mx0 = fmaxf(mx0, fmaxf(sacc[ni][0], sacc[ni][1]));
            mx1 = fmaxf(mx1, fmaxf(sacc[ni][2], sacc[ni][3]));
        }
        mx0 = fmaxf(mx0, __shfl_xor_sync(0xffffffffu, mx0, 1));
        mx0 = fmaxf(mx0, __shfl_xor_sync(0xffffffffu, mx0, 2));
        mx1 = fmaxf(mx1, __shfl_xor_sync(0xffffffffu, mx1, 1));
        mx1 = fmaxf(mx1, __shfl_xor_sync(0xffffffffu, mx1, 2));
        float mn0 = fmaxf(m_i[0], mx0);
        float mn1 = fmaxf(m_i[1], mx1);
        float al0 = __expf(m_i[0] - mn0);
        float al1 = __expf(m_i[1] - mn1);
        float ls0 = 0.f, ls1 = 0.f;
#pragma unroll
        for (int ni = 0; ni < 8; ++ni) {
            sacc[ni][0] = __expf(sacc[ni][0] - mn0);
            sacc[ni][1] = __expf(sacc[ni][1] - mn0);
            sacc[ni][2] = __expf(sacc[ni][2] - mn1);
            sacc[ni][3] = __expf(sacc[ni][3] - mn1);
            ls0 += sacc[ni][0] + sacc[ni][1];
            ls1 += sacc[ni][2] + sacc[ni][3];
        }
        ls0 += __shfl_xor_sync(0xffffffffu, ls0, 1);
        ls0 += __shfl_xor_sync(0xffffffffu, ls0, 2);
        ls1 += __shfl_xor_sync(0xffffffffu, ls1, 1);
        ls1 += __shfl_xor_sync(0xffffffffu, ls1, 2);
        l_i[0] = l_i[0] * al0 + ls0;
        l_i[1] = l_i[1] * al1 + ls1;
        m_i[0] = mn0;
        m_i[1] = mn1;
#pragma unroll
        for (int nj = 0; nj < 16; ++nj) {
            oacc[nj][0] *= al0; oacc[nj][1] *= al0;
            oacc[nj][2] *= al1; oacc[nj][3] *= al1;
        }

        // ---- O += P V: S-frags become A-frags directly ----
#pragma unroll
        for (int kc2 = 0; kc2 < 4; ++kc2) {
            uint32_t pa[4];
            pa[0] = packh2(sacc[2 * kc2][0],     sacc[2 * kc2][1]);
            pa[1] = packh2(sacc[2 * kc2][2],     sacc[2 * kc2][3]);
            pa[2] = packh2(sacc[2 * kc2 + 1][0], sacc[2 * kc2 + 1][1]);
            pa[3] = packh2(sacc[2 * kc2 + 1][2], sacc[2 * kc2 + 1][3]);
            uint32_t vb[8][4];
#pragma unroll
            for (int n2 = 0; n2 < 8; ++n2) {
                uint32_t boff = (uint32_t)(((n2 * 16 + b_row0) * AVP + (2 * kc2 + b_csel) * 8) * 2);
                ldsm4(vb[n2], smb + AT_VT + boff);
            }
#pragma unroll
            for (int nj = 0; nj < 16; ++nj)
                mma16816h(oacc[nj], pa, &vb[nj >> 1][(nj & 1) * 2]);
        }
    }

    // ---- epilogue: write fp16 attention output ----
    float inv0 = 1.f / l_i[0];
    float inv1 = 1.f / l_i[1];
    const int r0 = q0 + wid * 16 + gid;
    __half* op0 = O + ((size_t)(b * S + r0) * NH + h) * HD;
    __half* op1 = O + ((size_t)(b * S + r0 + 8) * NH + h) * HD;
#pragma unroll
    for (int nj = 0; nj < 16; ++nj) {
        int col = nj * 8 + 2 * tig;
        *(uint32_t*)(op0 + col) = packh2(oacc[nj][0] * inv0, oacc[nj][1] * inv0);
        *(uint32_t*)(op1 + col) = packh2(oacc[nj][2] * inv1, oacc[nj][3] * inv1);
    }
}

// ---------------- launch ----------------
extern "C" void kernel_launch(void* const* d_in, const int* in_sizes, int n_in,
                              void* d_out, int out_size) {
    const float* hs  = (const float*)d_in[0];
    const float* wq  = (const float*)d_in[1];
    const float* wk  = (const float*)d_in[2];
    const float* wv  = (const float*)d_in[3];
    const float* wo  = (const float*)d_in[4];
    const int*   pos = (const int*)  d_in[6];

    int nnz = in_sizes[0] / HID;
    int b   = in_sizes[10] - 1;
    int s   = nnz / b;

    float *q, *kt, *vt;
    cudaGetSymbolAddress((void**)&q,  g_q);
    cudaGetSymbolAddress((void**)&kt, g_kt);
    cudaGetSymbolAddress((void**)&vt, g_vt);

    __nv_bfloat16 *hsh, *hsl, *wqh, *wql, *wkh, *wkl;
    __half *hsh16, *wvh16, *woh, *ath;
    __half *qh16, *ql16, *kh16, *kl16, *vh16;
    cudaGetSymbolAddress((void**)&hsh,   g_hs_hi);
    cudaGetSymbolAddress((void**)&hsl,   g_hs_lo);
    cudaGetSymbolAddress((void**)&wqh,   g_wq_hi);
    cudaGetSymbolAddress((void**)&wql,   g_wq_lo);
    cudaGetSymbolAddress((void**)&wkh,   g_wk_hi);
    cudaGetSymbolAddress((void**)&wkl,   g_wk_lo);
    cudaGetSymbolAddress((void**)&hsh16, g_hs_h16);
    cudaGetSymbolAddress((void**)&wvh16, g_wv_h);
    cudaGetSymbolAddress((void**)&woh,   g_wo_h);
    cudaGetSymbolAddress((void**)&ath,   g_at_h);
    cudaGetSymbolAddress((void**)&qh16,  g_qh16);
    cudaGetSymbolAddress((void**)&ql16,  g_ql16);
    cudaGetSymbolAddress((void**)&kh16,  g_kh16);
    cudaGetSymbolAddress((void**)&kl16,  g_kl16);
    cudaGetSymbolAddress((void**)&vh16,  g_vh16);

    cudaFuncSetAttribute(attn_kernel, cudaFuncAttributeMaxDynamicSharedMemorySize,
                         ATTN_SMEM_B);
    cudaFuncSetAttribute(qkv_gemm, cudaFuncAttributeMaxDynamicSharedMemorySize, GEMM_SMEM);
    cudaFuncSetAttribute(hgemm_o,  cudaFuncAttributeMaxDynamicSharedMemorySize, 2 * 48 * 1024);

    // 1. RoPE cos/sin table
    rope_table_kernel<<<s, 64>>>();

    // 2. converts (hs: single read -> bf16 hi/lo + fp16 hi)
    {
        int n4;
        n4 = nnz * HID / 4;
        cvt_split_tri_kernel<<<(n4 + 255) / 256, 256>>>(hs, hsh, hsl, hsh16, n4);
        n4 = NH  * HD * HID / 4; cvt_split_kernel<<<(n4 + 255) / 256, 256>>>(wq, wqh, wql, n4);
        n4 = NKV * HD * HID / 4; cvt_split_kernel<<<(n4 + 255) / 256, 256>>>(wk, wkh, wkl, n4);
        n4 = NKV * HD * HID / 4; cvt_f16_kernel<<<(n4 + 255) / 256, 256>>>(wv, wvh16, n4);
        n4 = HID * NH * HD / 4;  cvt_f16_kernel<<<(n4 + 255) / 256, 256>>>(wo, woh, n4);
    }

    // 3. fused Q/K/V projection (Q,K 3xbf16; V 1-term fp16), BM=256 tiles
    qkv_gemm<<<dim3(48, nnz / BM), 256, GEMM_SMEM>>>(hsh, hsl, wqh, wql, wkh, wkl,
                                                     hsh16, wvh16, q, kt, vt);

    // 4. RoPE -> fp16 splits + paged-KV gather-scatter
    rope_q_kernel<<<nnz, 256>>>(q, qh16, ql16, pos);
    ropekv_scatter_kernel<<<nnz, 256>>>(pos, s);

    // 5. HMMA flash attention (3-term fp16 QK^T, fp16 PV) -> fp16 out
    float scale = 1.0f / sqrtf((float)HD);
    attn_kernel<<<dim3(s / 128, NH, b), 256, ATTN_SMEM_B>>>(qh16, ql16, kh16, kl16,
                                                            vh16, ath, s, scale);

    // 6. output projection (1-term fp16)
    hgemm_o<<<dim3(HID / BN, nnz / BM), 256, 2 * 48 * 1024>>>(ath, woh,
                                                              (float*)d_out, HID, NH * HD);
}